// round 2
// baseline (speedup 1.0000x reference)
#include <cuda_runtime.h>
#include <math.h>

// ---------------------------------------------------------------------------
// MinGPT forward.  B=4, S=1024, D=1024, H=16, HS=64, L=4, DFF=4096, V=32000.
// Round 2: packed f32x2 FFMA GEMM + query-tiled attention.
// ---------------------------------------------------------------------------

#define B_  4
#define S_  1024
#define D_  1024
#define H_  16
#define HS_ 64
#define L_  4
#define DFF_ 4096
#define V_  32000
#define M_  (B_ * S_)
#define EPS_ 1e-5f
#define SCALE_ 0.03125f        // D^-0.5 = 1/32 (reference uses d_model)

// ------------------------- scratch -----------------------------------------
__device__ float g_x  [M_ * D_];
__device__ float g_xn [M_ * D_];
__device__ float g_q  [M_ * D_];
__device__ float g_k  [M_ * D_];
__device__ float g_v  [M_ * D_];
__device__ float g_att[M_ * D_];
__device__ float g_h  [M_ * DFF_];

// ------------------------- f32x2 helpers ------------------------------------
__device__ __forceinline__ unsigned long long pk2(float lo, float hi) {
    unsigned long long r;
    asm("mov.b64 %0, {%1, %2};" : "=l"(r) : "f"(lo), "f"(hi));
    return r;
}
__device__ __forceinline__ void fma2(unsigned long long& d,
                                     unsigned long long a, unsigned long long b) {
    asm("fma.rn.f32x2 %0, %1, %2, %0;" : "+l"(d) : "l"(a), "l"(b));
}
__device__ __forceinline__ float2 up2(unsigned long long v) {
    float2 r;
    asm("mov.b64 {%0, %1}, %2;" : "=f"(r.x), "=f"(r.y) : "l"(v));
    return r;
}

// ------------------------- embedding ----------------------------------------
__global__ __launch_bounds__(256) void embed_k(
    const int* __restrict__ idx, const float4* __restrict__ tok,
    const float4* __restrict__ pos, float4* __restrict__ x)
{
    int row = blockIdx.x;
    int s   = row & (S_ - 1);
    int t   = idx[row];
    int c   = threadIdx.x;
    float4 tv = tok[(size_t)t * (D_ / 4) + c];
    float4 pv = pos[(size_t)s * (D_ / 4) + c];
    float4 o;
    o.x = tv.x + pv.x; o.y = tv.y + pv.y; o.z = tv.z + pv.z; o.w = tv.w + pv.w;
    x[(size_t)row * (D_ / 4) + c] = o;
}

// ------------------------- layer norm ---------------------------------------
__global__ __launch_bounds__(256) void layernorm_k(
    const float4* __restrict__ x, const float4* __restrict__ g,
    const float4* __restrict__ bb, float4* __restrict__ y)
{
    int row = blockIdx.x;
    int tid = threadIdx.x;
    __shared__ float red[256];

    float4 xv = x[(size_t)row * 256 + tid];

    float s = xv.x + xv.y + xv.z + xv.w;
    red[tid] = s; __syncthreads();
    #pragma unroll
    for (int st = 128; st > 0; st >>= 1) {
        if (tid < st) red[tid] += red[tid + st];
        __syncthreads();
    }
    float mu = red[0] * (1.0f / D_);
    __syncthreads();

    float dx = xv.x - mu, dy = xv.y - mu, dz = xv.z - mu, dw = xv.w - mu;
    float s2 = dx * dx + dy * dy + dz * dz + dw * dw;
    red[tid] = s2; __syncthreads();
    #pragma unroll
    for (int st = 128; st > 0; st >>= 1) {
        if (tid < st) red[tid] += red[tid + st];
        __syncthreads();
    }
    float var = red[0] * (1.0f / D_);
    float inv = rsqrtf(var + EPS_);

    float4 gv = g[tid], bv = bb[tid];
    float4 o;
    o.x = dx * inv * gv.x + bv.x;
    o.y = dy * inv * gv.y + bv.y;
    o.z = dz * inv * gv.z + bv.z;
    o.w = dw * inv * gv.w + bv.w;
    y[(size_t)row * 256 + tid] = o;
}

// ------------------------- SGEMM with packed f32x2 FFMA ---------------------
// C[M,N] = A[M,K] @ B[K,N] (+bias)(+res)(relu)
// 128x128 block, BK=16, 8x8 per thread (acc packed in M-pairs), 256 threads.
template<bool BIAS, bool RES, bool RELU>
__global__ __launch_bounds__(256) void sgemm2_k(
    int M, int N, int K,
    const float* __restrict__ A, const float* __restrict__ B,
    const float* __restrict__ bias, const float* __restrict__ res,
    float* __restrict__ C)
{
    const int BM = 128, BN = 128, BK = 16, TM = 8, TN = 8;
    __shared__ float As[BK][BM + 4];                 // transposed A tile
    __shared__ unsigned long long Bs2[BK][BN];       // B tile, each val duplicated

    int tid = threadIdx.x;
    int cRow = blockIdx.y, cCol = blockIdx.x;

    int threadCol = tid % (BN / TN);   // 0..15
    int threadRow = tid / (BN / TN);   // 0..15

    const float* Ap = A + (size_t)cRow * BM * K;
    const float* Bp = B + (size_t)cCol * BN;
    float*       Cp = C + (size_t)cRow * BM * N + (size_t)cCol * BN;
    const float* Rp = RES  ? res  + (size_t)cRow * BM * N + (size_t)cCol * BN : nullptr;
    const float* bp = BIAS ? bias + (size_t)cCol * BN : nullptr;

    int aRow = tid / 4;                // 0..63 (2 passes of 64 rows)
    int aCol = tid % 4;                // *4 floats over BK=16

    unsigned long long acc2[TM / 2][TN];
    #pragma unroll
    for (int i = 0; i < TM / 2; i++)
        #pragma unroll
        for (int j = 0; j < TN; j++) acc2[i][j] = 0ULL;

    for (int k0 = 0; k0 < K; k0 += BK) {
        // A tile: load coalesced, store transposed
        #pragma unroll
        for (int off = 0; off < BM; off += 64) {
            float4 t = *(const float4*)(Ap + (size_t)(aRow + off) * K + aCol * 4);
            As[aCol * 4 + 0][aRow + off] = t.x;
            As[aCol * 4 + 1][aRow + off] = t.y;
            As[aCol * 4 + 2][aRow + off] = t.z;
            As[aCol * 4 + 3][aRow + off] = t.w;
        }
        // B tile: load coalesced float2, store each value duplicated as 8B pair
        #pragma unroll
        for (int e = 0; e < (BK * BN / 2); e += 256) {
            int ee = e + tid;
            int kk = ee >> 6;             // 64 float2 per 128-wide row
            int nn = (ee & 63) * 2;
            float2 bv = *(const float2*)(Bp + (size_t)kk * N + nn);
            Bs2[kk][nn + 0] = pk2(bv.x, bv.x);
            Bs2[kk][nn + 1] = pk2(bv.y, bv.y);
        }
        __syncthreads();
        Ap += BK;
        Bp += (size_t)BK * N;

        #pragma unroll
        for (int k = 0; k < BK; k++) {
            unsigned long long a2[TM / 2];
            #pragma unroll
            for (int ip = 0; ip < TM / 2; ip++)
                a2[ip] = *(const unsigned long long*)(&As[k][threadRow * TM + 2 * ip]);
            #pragma unroll
            for (int j = 0; j < TN; j++) {
                unsigned long long b2 = Bs2[k][threadCol * TN + j];
                #pragma unroll
                for (int ip = 0; ip < TM / 2; ip++)
                    fma2(acc2[ip][j], a2[ip], b2);
            }
        }
        __syncthreads();
    }

    // epilogue: unpack row pairs, fuse bias/res/relu, float4 stores
    #pragma unroll
    for (int ip = 0; ip < TM / 2; ip++) {
        int r0 = threadRow * TM + 2 * ip;
        float v0[TN], v1[TN];
        #pragma unroll
        for (int j = 0; j < TN; j++) {
            float2 u = up2(acc2[ip][j]);
            v0[j] = u.x; v1[j] = u.y;
        }
        #pragma unroll
        for (int half = 0; half < 2; half++) {
            int r = r0 + half;
            float* vv = half ? v1 : v0;
            #pragma unroll
            for (int j = 0; j < TN; j += 4) {
                int c = threadCol * TN + j;
                float4 o;
                o.x = vv[j + 0]; o.y = vv[j + 1]; o.z = vv[j + 2]; o.w = vv[j + 3];
                if (BIAS) {
                    o.x += bp[c + 0]; o.y += bp[c + 1];
                    o.z += bp[c + 2]; o.w += bp[c + 3];
                }
                if (RES) {
                    float4 rv = *(const float4*)(Rp + (size_t)r * N + c);
                    o.x += rv.x; o.y += rv.y; o.z += rv.z; o.w += rv.w;
                }
                if (RELU) {
                    o.x = fmaxf(o.x, 0.0f); o.y = fmaxf(o.y, 0.0f);
                    o.z = fmaxf(o.z, 0.0f); o.w = fmaxf(o.w, 0.0f);
                }
                *(float4*)(Cp + (size_t)r * N + c) = o;
            }
        }
    }
}

// ------------------------- query-tiled causal attention ---------------------
// One block = 8 queries x one head x one batch.  256 threads.
// K rows read once per block (8x amortization), V rows once per block.
#define QT_   8
#define SPAD_ 1032
__global__ __launch_bounds__(256) void attention2_k(
    const float* __restrict__ q, const float* __restrict__ k,
    const float* __restrict__ v, float* __restrict__ o)
{
    int qt = blockIdx.x, h = blockIdx.y, b = blockIdx.z;
    int q0 = qt * QT_;
    int nmax = q0 + QT_;                 // covers all causal bounds in tile
    int tid = threadIdx.x;

    __shared__ float S[QT_][SPAD_];      // scores -> probs -> (reused) partials
    __shared__ float Rinv[QT_];

    // ---- phase 1: scores.  thread: qi = tid&7, jg = tid>>3 (32 j-slots) ----
    {
        int qi = tid & 7;
        int jg = tid >> 3;
        const float* qp = q + (((size_t)b * S_ + q0 + qi) * H_ + h) * HS_;
        float4 qr[16];
        #pragma unroll
        for (int d = 0; d < 16; d++) qr[d] = *(const float4*)(qp + 4 * d);

        int nq = q0 + qi + 1;            // causal bound for this query
        for (int j = jg; j < nq; j += 32) {
            const float* kp = k + (((size_t)b * S_ + j) * H_ + h) * HS_;
            float dot = 0.0f;
            #pragma unroll
            for (int d = 0; d < 16; d++) {
                float4 kk = *(const float4*)(kp + 4 * d);
                dot += kk.x * qr[d].x + kk.y * qr[d].y + kk.z * qr[d].z + kk.w * qr[d].w;
            }
            S[qi][j] = dot * SCALE_;
        }
    }
    __syncthreads();

    // ---- phase 2: softmax per row.  warp w handles query w ----
    {
        int w = tid >> 5, l = tid & 31;
        int nq = q0 + w + 1;
        float m = -1e30f;
        for (int j = l; j < nq; j += 32) m = fmaxf(m, S[w][j]);
        #pragma unroll
        for (int st = 16; st > 0; st >>= 1)
            m = fmaxf(m, __shfl_xor_sync(0xffffffff, m, st));
        float sum = 0.0f;
        for (int j = l; j < nq; j += 32) {
            float e = __expf(S[w][j] - m);
            S[w][j] = e;
            sum += e;
        }
        #pragma unroll
        for (int st = 16; st > 0; st >>= 1)
            sum += __shfl_xor_sync(0xffffffff, sum, st);
        for (int j = nq + l; j < nmax; j += 32) S[w][j] = 0.0f;  // pad causal tail
        if (l == 0) Rinv[w] = 1.0f / sum;
    }
    __syncthreads();

    // ---- phase 3: O = P @ V.  thread: d4 = tid&15, jg = tid>>4 (16 slots) --
    float acc[QT_][4];
    {
        int d4 = tid & 15;
        int jg = tid >> 4;
        #pragma unroll
        for (int qi = 0; qi < QT_; qi++)
            #pragma unroll
            for (int c = 0; c < 4; c++) acc[qi][c] = 0.0f;

        for (int j = jg; j < nmax; j += 16) {
            float4 vv = *(const float4*)(v + (((size_t)b * S_ + j) * H_ + h) * HS_ + d4 * 4);
            #pragma unroll
            for (int qi = 0; qi < QT_; qi++) {
                float p = S[qi][j];
                acc[qi][0] += p * vv.x; acc[qi][1] += p * vv.y;
                acc[qi][2] += p * vv.z; acc[qi][3] += p * vv.w;
            }
        }
    }
    __syncthreads();

    // scatter partials into S (reused as scratch), reduce over 16 jg groups
    {
        int d4 = tid & 15;
        int jg = tid >> 4;
        float* scratch = &S[0][0];
        #pragma unroll
        for (int qi = 0; qi < QT_; qi++)
            #pragma unroll
            for (int c = 0; c < 4; c++)
                scratch[jg * 512 + qi * 64 + d4 * 4 + c] = acc[qi][c];
    }
    __syncthreads();
    {
        const float* scratch = &S[0][0];
        #pragma unroll
        for (int e = tid; e < 512; e += 256) {
            int qi = e >> 6, d = e & 63;
            float sum = 0.0f;
            #pragma unroll
            for (int jg = 0; jg < 16; jg++) sum += scratch[jg * 512 + qi * 64 + d];
            o[(((size_t)b * S_ + q0 + qi) * H_ + h) * HS_ + d] = sum * Rinv[qi];
        }
    }
}

// ------------------------- driver -------------------------------------------
extern "C" void kernel_launch(void* const* d_in, const int* in_sizes, int n_in,
                              void* d_out, int out_size)
{
    const int*   idx   = (const int*)  d_in[0];
    const float* tok   = (const float*)d_in[1];
    const float* pos   = (const float*)d_in[2];
    const float* ln1g  = (const float*)d_in[3];
    const float* ln1b  = (const float*)d_in[4];
    const float* ln2g  = (const float*)d_in[5];
    const float* ln2b  = (const float*)d_in[6];
    const float* wq    = (const float*)d_in[7];
    const float* wk    = (const float*)d_in[8];
    const float* wv    = (const float*)d_in[9];
    const float* wo    = (const float*)d_in[10];
    const float* bo    = (const float*)d_in[11];
    const float* w1    = (const float*)d_in[12];
    const float* b1    = (const float*)d_in[13];
    const float* w2    = (const float*)d_in[14];
    const float* b2    = (const float*)d_in[15];
    const float* lnfg  = (const float*)d_in[16];
    const float* lnfb  = (const float*)d_in[17];
    const float* whead = (const float*)d_in[18];
    const float* bhead = (const float*)d_in[19];
    float* out = (float*)d_out;

    float *x, *xn, *q, *k, *v, *att, *hb;
    cudaGetSymbolAddress((void**)&x,   g_x);
    cudaGetSymbolAddress((void**)&xn,  g_xn);
    cudaGetSymbolAddress((void**)&q,   g_q);
    cudaGetSymbolAddress((void**)&k,   g_k);
    cudaGetSymbolAddress((void**)&v,   g_v);
    cudaGetSymbolAddress((void**)&att, g_att);
    cudaGetSymbolAddress((void**)&hb,  g_h);

    dim3 blk(256);
    embed_k<<<M_, blk>>>(idx, (const float4*)tok, (const float4*)pos, (float4*)x);

    for (int l = 0; l < L_; l++) {
        layernorm_k<<<M_, blk>>>((const float4*)x, (const float4*)(ln1g + l * D_),
                                 (const float4*)(ln1b + l * D_), (float4*)xn);

        dim3 gQ(D_ / 128, M_ / 128);
        sgemm2_k<false,false,false><<<gQ, blk>>>(M_, D_, D_, xn, wq + (size_t)l*D_*D_, nullptr, nullptr, q);
        sgemm2_k<false,false,false><<<gQ, blk>>>(M_, D_, D_, xn, wk + (size_t)l*D_*D_, nullptr, nullptr, k);
        sgemm2_k<false,false,false><<<gQ, blk>>>(M_, D_, D_, xn, wv + (size_t)l*D_*D_, nullptr, nullptr, v);

        attention2_k<<<dim3(S_ / QT_, H_, B_), 256>>>(q, k, v, att);

        // x = xn + att @ wo + bo
        sgemm2_k<true,true,false><<<gQ, blk>>>(M_, D_, D_, att, wo + (size_t)l*D_*D_,
                                               bo + l * D_, xn, x);

        layernorm_k<<<M_, blk>>>((const float4*)x, (const float4*)(ln2g + l * D_),
                                 (const float4*)(ln2b + l * D_), (float4*)xn);

        // h = relu(xn @ w1 + b1)
        sgemm2_k<true,false,true><<<dim3(DFF_/128, M_/128), blk>>>(
            M_, DFF_, D_, xn, w1 + (size_t)l*D_*DFF_, b1 + l * DFF_, nullptr, hb);

        // x = xn + h @ w2 + b2
        sgemm2_k<true,true,false><<<dim3(D_/128, M_/128), blk>>>(
            M_, D_, DFF_, hb, w2 + (size_t)l*DFF_*D_, b2 + l * D_, xn, x);
    }

    layernorm_k<<<M_, blk>>>((const float4*)x, (const float4*)lnfg,
                             (const float4*)lnfb, (float4*)xn);

    sgemm2_k<true,false,false><<<dim3(V_/128, M_/128), blk>>>(
        M_, V_, D_, xn, whead, bhead, nullptr, out);
}

// round 4
// speedup vs baseline: 5.0188x; 5.0188x over previous
#include <cuda_runtime.h>
#include <cuda_bf16.h>
#include <cstdint>
#include <math.h>

// ---------------------------------------------------------------------------
// MinGPT forward.  B=4, S=1024, D=1024, H=16, HS=64, L=4, DFF=4096, V=32000.
// Round 4: mma.sync bf16 (m16n8k16) hi/lo-split GEMM + query-tiled attention.
// (tcgen05 unavailable: harness PTX targets compute_103, not 103a.)
// ---------------------------------------------------------------------------

#define B_  4
#define S_  1024
#define D_  1024
#define H_  16
#define HS_ 64
#define L_  4
#define DFF_ 4096
#define V_  32000
#define M_  (B_ * S_)
#define EPS_ 1e-5f
#define SCALE_ 0.03125f        // D^-0.5 = 1/32 (reference uses d_model)

// ------------------------- scratch -----------------------------------------
__device__ float g_x  [M_ * D_];
__device__ float g_xn [M_ * D_];
__device__ float g_q  [M_ * D_];
__device__ float g_k  [M_ * D_];
__device__ float g_v  [M_ * D_];
__device__ float g_att[M_ * D_];
__device__ float g_h  [M_ * DFF_];

// activation hi/lo (max M x DFF)
__device__ __align__(16) __nv_bfloat16 g_ah[M_ * DFF_];
__device__ __align__(16) __nv_bfloat16 g_al[M_ * DFF_];

// transposed weights hi/lo: [N,K] layouts, all matrices packed
#define DD_      ((size_t)D_ * D_)
#define PER_L_   (4 * DD_ + 2 * (size_t)D_ * DFF_)
#define WT_TOT_  (4 * PER_L_ + (size_t)D_ * V_)
__device__ __align__(16) __nv_bfloat16 g_wh[WT_TOT_];
__device__ __align__(16) __nv_bfloat16 g_wl[WT_TOT_];

// ------------------------- PTX helpers (all sm_80-level, no 'a' features) ---
__device__ __forceinline__ uint32_t smem_u32(const void* p) {
    uint32_t a;
    asm("{ .reg .u64 t; cvta.to.shared.u64 t, %1; cvt.u32.u64 %0, t; }"
        : "=r"(a) : "l"(p));
    return a;
}
#define CP16(dst, src) \
    asm volatile("cp.async.cg.shared.global [%0], [%1], 16;" :: "r"(dst), "l"(src))
#define CPCOMMIT() asm volatile("cp.async.commit_group;" ::: "memory")
#define CPWAIT0()  asm volatile("cp.async.wait_group 0;" ::: "memory")
#define CPWAIT1()  asm volatile("cp.async.wait_group 1;" ::: "memory")

__device__ __forceinline__ void ldsm4(uint32_t* r, uint32_t addr) {
    asm volatile("ldmatrix.sync.aligned.m8n8.x4.shared.b16 {%0,%1,%2,%3}, [%4];"
        : "=r"(r[0]), "=r"(r[1]), "=r"(r[2]), "=r"(r[3]) : "r"(addr));
}
__device__ __forceinline__ void ldsm2(uint32_t* r, uint32_t addr) {
    asm volatile("ldmatrix.sync.aligned.m8n8.x2.shared.b16 {%0,%1}, [%2];"
        : "=r"(r[0]), "=r"(r[1]) : "r"(addr));
}
__device__ __forceinline__ void mma16816(float* d, const uint32_t* a, const uint32_t* b) {
    asm volatile(
        "mma.sync.aligned.m16n8k16.row.col.f32.bf16.bf16.f32 "
        "{%0,%1,%2,%3}, {%4,%5,%6,%7}, {%8,%9}, {%0,%1,%2,%3};"
        : "+f"(d[0]), "+f"(d[1]), "+f"(d[2]), "+f"(d[3])
        : "r"(a[0]), "r"(a[1]), "r"(a[2]), "r"(a[3]), "r"(b[0]), "r"(b[1]));
}

// ------------------------- embedding ----------------------------------------
__global__ __launch_bounds__(256) void embed_k(
    const int* __restrict__ idx, const float4* __restrict__ tok,
    const float4* __restrict__ pos, float4* __restrict__ x)
{
    int row = blockIdx.x;
    int s   = row & (S_ - 1);
    int t   = idx[row];
    int c   = threadIdx.x;
    float4 tv = tok[(size_t)t * (D_ / 4) + c];
    float4 pv = pos[(size_t)s * (D_ / 4) + c];
    float4 o;
    o.x = tv.x + pv.x; o.y = tv.y + pv.y; o.z = tv.z + pv.z; o.w = tv.w + pv.w;
    x[(size_t)row * (D_ / 4) + c] = o;
}

// ------------------------- layer norm ---------------------------------------
__global__ __launch_bounds__(256) void layernorm_k(
    const float4* __restrict__ x, const float4* __restrict__ g,
    const float4* __restrict__ bb, float4* __restrict__ y)
{
    int row = blockIdx.x;
    int tid = threadIdx.x;
    __shared__ float red[256];

    float4 xv = x[(size_t)row * 256 + tid];
    float s = xv.x + xv.y + xv.z + xv.w;
    red[tid] = s; __syncthreads();
    #pragma unroll
    for (int st = 128; st > 0; st >>= 1) {
        if (tid < st) red[tid] += red[tid + st];
        __syncthreads();
    }
    float mu = red[0] * (1.0f / D_);
    __syncthreads();

    float dx = xv.x - mu, dy = xv.y - mu, dz = xv.z - mu, dw = xv.w - mu;
    float s2 = dx * dx + dy * dy + dz * dz + dw * dw;
    red[tid] = s2; __syncthreads();
    #pragma unroll
    for (int st = 128; st > 0; st >>= 1) {
        if (tid < st) red[tid] += red[tid + st];
        __syncthreads();
    }
    float inv = rsqrtf(red[0] * (1.0f / D_) + EPS_);

    float4 gv = g[tid], bv = bb[tid];
    float4 o;
    o.x = dx * inv * gv.x + bv.x;
    o.y = dy * inv * gv.y + bv.y;
    o.z = dz * inv * gv.z + bv.z;
    o.w = dw * inv * gv.w + bv.w;
    y[(size_t)row * 256 + tid] = o;
}

// ------------------------- fp32 -> bf16 hi/lo split --------------------------
__global__ __launch_bounds__(256) void split_k(
    const float4* __restrict__ x, __nv_bfloat162* __restrict__ h,
    __nv_bfloat162* __restrict__ l, int n4)
{
    int i = blockIdx.x * 256 + threadIdx.x;
    if (i >= n4) return;
    float4 v = x[i];
    __nv_bfloat16 hx = __float2bfloat16_rn(v.x);
    __nv_bfloat16 hy = __float2bfloat16_rn(v.y);
    __nv_bfloat16 hz = __float2bfloat16_rn(v.z);
    __nv_bfloat16 hw = __float2bfloat16_rn(v.w);
    __nv_bfloat162 h0; h0.x = hx; h0.y = hy;
    __nv_bfloat162 h1; h1.x = hz; h1.y = hw;
    __nv_bfloat162 l0, l1;
    l0.x = __float2bfloat16_rn(v.x - __bfloat162float(hx));
    l0.y = __float2bfloat16_rn(v.y - __bfloat162float(hy));
    l1.x = __float2bfloat16_rn(v.z - __bfloat162float(hz));
    l1.y = __float2bfloat16_rn(v.w - __bfloat162float(hw));
    h[2 * i] = h0; h[2 * i + 1] = h1;
    l[2 * i] = l0; l[2 * i + 1] = l1;
}

// ------------------------- weight transpose + split --------------------------
__global__ __launch_bounds__(256) void wtrans_k(
    const float* __restrict__ W, __nv_bfloat16* __restrict__ Th,
    __nv_bfloat16* __restrict__ Tl, int K, int N)
{
    __shared__ float t[32][33];
    int n0 = blockIdx.x * 32, k0 = blockIdx.y * 32;
    int tx = threadIdx.x, ty = threadIdx.y;
    #pragma unroll
    for (int i = 0; i < 4; i++)
        t[ty + i * 8][tx] = W[(size_t)(k0 + ty + i * 8) * N + n0 + tx];
    __syncthreads();
    #pragma unroll
    for (int i = 0; i < 4; i++) {
        float v = t[tx][ty + i * 8];
        __nv_bfloat16 h = __float2bfloat16_rn(v);
        size_t o = (size_t)(n0 + ty + i * 8) * K + k0 + tx;
        Th[o] = h;
        Tl[o] = __float2bfloat16_rn(v - __bfloat162float(h));
    }
}

// ------------------------- mma.sync GEMM ------------------------------------
// C[M,N] = (Ah+Al)[M,K] @ ((Bh+Bl)[N,K])^T  (+bias)(+res)(relu), fp32 out.
// CTA 128x128, BK=64 (128B rows, SW128 swizzle), 8 warps = 2(M) x 4(N),
// warp tile 64x32, double-buffered cp.async.  3 products: AhBh + AlBh + AhBl.
#define TILEB_ 16384                       // one 128x64 bf16 tile
#define BUFB_  (4 * TILEB_)                // Ah,Al,Bh,Bl
#define SMTOT_ (2 * BUFB_)                 // double buffer = 128 KB

template<bool BIAS, bool RES, bool RELU>
__global__ __launch_bounds__(256) void mma_gemm_k(
    int M, int N, int K,
    const __nv_bfloat16* __restrict__ Ah, const __nv_bfloat16* __restrict__ Al,
    const __nv_bfloat16* __restrict__ Bh, const __nv_bfloat16* __restrict__ Bl,
    const float* __restrict__ bias, const float* __restrict__ res,
    float* __restrict__ C)
{
    extern __shared__ char smem[];
    const uint32_t sb = smem_u32(smem);
    const int tid = threadIdx.x, wid = tid >> 5, lane = tid & 31;
    const int mb = blockIdx.x, nb = blockIdx.y;
    const size_t ar0 = (size_t)mb * 128, br0 = (size_t)nb * 128;
    const int wm = (wid >> 2) * 64, wn = (wid & 3) * 32;

    float acc[4][4][4];
    #pragma unroll
    for (int i = 0; i < 4; i++)
        #pragma unroll
        for (int j = 0; j < 4; j++)
            #pragma unroll
            for (int e = 0; e < 4; e++) acc[i][j][e] = 0.0f;

    const int nch = K >> 6;

    // ---- async fill of one buffer for chunk c ----
    auto fill = [&](int buf, int c) {
        const size_t kof = (size_t)c << 6;
        const uint32_t bb = sb + buf * BUFB_;
        #pragma unroll
        for (int i = 0; i < 4; i++) {
            int id = tid + 256 * i;          // 0..1023
            int r  = id >> 3;                // row 0..127
            int cx = id & 7;                 // 16B chunk
            uint32_t so = (uint32_t)(r * 128 + cx * 16);
            so ^= (so >> 3) & 0x70;
            size_t ai = (ar0 + r) * (size_t)K + kof + cx * 8;
            size_t bi = (br0 + r) * (size_t)K + kof + cx * 8;
            CP16(bb + 0 * TILEB_ + so, Ah + ai);
            CP16(bb + 1 * TILEB_ + so, Al + ai);
            CP16(bb + 2 * TILEB_ + so, Bh + bi);
            CP16(bb + 3 * TILEB_ + so, Bl + bi);
        }
    };

    fill(0, 0); CPCOMMIT();

    for (int c = 0; c < nch; c++) {
        if (c + 1 < nch) { fill((c + 1) & 1, c + 1); CPCOMMIT(); CPWAIT1(); }
        else             { CPWAIT0(); }
        __syncthreads();

        const uint32_t base = sb + (c & 1) * BUFB_;
        #pragma unroll
        for (int ks = 0; ks < 4; ks++) {
            uint32_t a_h[4][4], a_l[4][4], b_h[4][2], b_l[4][2];
            // A fragments: lanes 0-15 -> m rows, lane/16 -> k-half
            const int arow = wm + (lane & 15);
            const int akb  = ks * 32 + (lane >> 4) * 16;
            #pragma unroll
            for (int i = 0; i < 4; i++) {
                uint32_t so = (uint32_t)((arow + i * 16) * 128 + akb);
                so ^= (so >> 3) & 0x70;
                ldsm4(a_h[i], base + 0 * TILEB_ + so);
                ldsm4(a_l[i], base + 1 * TILEB_ + so);
            }
            // B fragments: lanes 0-7 -> n rows (k lo), 8-15 -> n rows (k hi)
            const int brow = wn + (lane & 7);
            const int bkb  = ks * 32 + ((lane >> 3) & 1) * 16;
            #pragma unroll
            for (int j = 0; j < 4; j++) {
                uint32_t so = (uint32_t)((brow + j * 8) * 128 + bkb);
                so ^= (so >> 3) & 0x70;
                ldsm2(b_h[j], base + 2 * TILEB_ + so);
                ldsm2(b_l[j], base + 3 * TILEB_ + so);
            }
            #pragma unroll
            for (int i = 0; i < 4; i++)
                #pragma unroll
                for (int j = 0; j < 4; j++) {
                    mma16816(acc[i][j], a_h[i], b_h[j]);
                    mma16816(acc[i][j], a_l[i], b_h[j]);
                    mma16816(acc[i][j], a_h[i], b_l[j]);
                }
        }
        __syncthreads();
    }

    // ---- epilogue: direct float2 stores, fused bias/res/relu ----
    const int g  = lane >> 2, tg = lane & 3;
    const size_t row0 = ar0 + wm, col0 = br0 + wn;
    #pragma unroll
    for (int i = 0; i < 4; i++) {
        #pragma unroll
        for (int j = 0; j < 4; j++) {
            size_t col = col0 + j * 8 + tg * 2;
            float bx = 0.0f, by = 0.0f;
            if (BIAS) { bx = bias[col]; by = bias[col + 1]; }
            #pragma unroll
            for (int half = 0; half < 2; half++) {
                size_t row = row0 + i * 16 + g + half * 8;
                float vx = acc[i][j][2 * half + 0] + bx;
                float vy = acc[i][j][2 * half + 1] + by;
                size_t gi = row * (size_t)N + col;
                if (RES) { vx += res[gi]; vy += res[gi + 1]; }
                if (RELU) { vx = fmaxf(vx, 0.0f); vy = fmaxf(vy, 0.0f); }
                float2 o; o.x = vx; o.y = vy;
                *(float2*)(C + gi) = o;
            }
        }
    }
}

// ------------------------- query-tiled causal attention ---------------------
#define QT_   8
#define SPAD_ 1032
__global__ __launch_bounds__(256) void attention2_k(
    const float* __restrict__ q, const float* __restrict__ k,
    const float* __restrict__ v, float* __restrict__ o)
{
    int qt = blockIdx.x, h = blockIdx.y, b = blockIdx.z;
    int q0 = qt * QT_;
    int nmax = q0 + QT_;
    int tid = threadIdx.x;

    __shared__ float S[QT_][SPAD_];
    __shared__ float Rinv[QT_];

    {
        int qi = tid & 7;
        int jg = tid >> 3;
        const float* qp = q + (((size_t)b * S_ + q0 + qi) * H_ + h) * HS_;
        float4 qr[16];
        #pragma unroll
        for (int d = 0; d < 16; d++) qr[d] = *(const float4*)(qp + 4 * d);
        int nq = q0 + qi + 1;
        for (int j = jg; j < nq; j += 32) {
            const float* kp = k + (((size_t)b * S_ + j) * H_ + h) * HS_;
            float dot = 0.0f;
            #pragma unroll
            for (int d = 0; d < 16; d++) {
                float4 kk = *(const float4*)(kp + 4 * d);
                dot += kk.x * qr[d].x + kk.y * qr[d].y + kk.z * qr[d].z + kk.w * qr[d].w;
            }
            S[qi][j] = dot * SCALE_;
        }
    }
    __syncthreads();

    {
        int w = tid >> 5, l = tid & 31;
        int nq = q0 + w + 1;
        float m = -1e30f;
        for (int j = l; j < nq; j += 32) m = fmaxf(m, S[w][j]);
        #pragma unroll
        for (int st = 16; st > 0; st >>= 1)
            m = fmaxf(m, __shfl_xor_sync(0xffffffff, m, st));
        float sum = 0.0f;
        for (int j = l; j < nq; j += 32) {
            float e = __expf(S[w][j] - m);
            S[w][j] = e;
            sum += e;
        }
        #pragma unroll
        for (int st = 16; st > 0; st >>= 1)
            sum += __shfl_xor_sync(0xffffffff, sum, st);
        for (int j = nq + l; j < nmax; j += 32) S[w][j] = 0.0f;
        if (l == 0) Rinv[w] = 1.0f / sum;
    }
    __syncthreads();

    float acc[QT_][4];
    {
        int d4 = tid & 15;
        int jg = tid >> 4;
        #pragma unroll
        for (int qi = 0; qi < QT_; qi++)
            #pragma unroll
            for (int cc = 0; cc < 4; cc++) acc[qi][cc] = 0.0f;
        for (int j = jg; j < nmax; j += 16) {
            float4 vv = *(const float4*)(v + (((size_t)b * S_ + j) * H_ + h) * HS_ + d4 * 4);
            #pragma unroll
            for (int qi = 0; qi < QT_; qi++) {
                float p = S[qi][j];
                acc[qi][0] += p * vv.x; acc[qi][1] += p * vv.y;
                acc[qi][2] += p * vv.z; acc[qi][3] += p * vv.w;
            }
        }
    }
    __syncthreads();
    {
        int d4 = tid & 15;
        int jg = tid >> 4;
        float* scratch = &S[0][0];
        #pragma unroll
        for (int qi = 0; qi < QT_; qi++)
            #pragma unroll
            for (int cc = 0; cc < 4; cc++)
                scratch[jg * 512 + qi * 64 + d4 * 4 + cc] = acc[qi][cc];
    }
    __syncthreads();
    {
        const float* scratch = &S[0][0];
        #pragma unroll
        for (int e = tid; e < 512; e += 256) {
            int qi = e >> 6, d = e & 63;
            float sum = 0.0f;
            #pragma unroll
            for (int jg = 0; jg < 16; jg++) sum += scratch[jg * 512 + qi * 64 + d];
            o[(((size_t)b * S_ + q0 + qi) * H_ + h) * HS_ + d] = sum * Rinv[qi];
        }
    }
}

// ------------------------- driver -------------------------------------------
static void gemm_launch(int M, int N, int K,
    const __nv_bfloat16* Ah, const __nv_bfloat16* Al,
    const __nv_bfloat16* Bh, const __nv_bfloat16* Bl,
    const float* bias, const float* res, float* C,
    int bias_f, int res_f, int relu_f)
{
    dim3 g(M / 128, N / 128);
    if (bias_f && res_f)
        mma_gemm_k<true, true, false><<<g, 256, SMTOT_>>>(M, N, K, Ah, Al, Bh, Bl, bias, res, C);
    else if (bias_f && relu_f)
        mma_gemm_k<true, false, true><<<g, 256, SMTOT_>>>(M, N, K, Ah, Al, Bh, Bl, bias, nullptr, C);
    else if (bias_f)
        mma_gemm_k<true, false, false><<<g, 256, SMTOT_>>>(M, N, K, Ah, Al, Bh, Bl, bias, nullptr, C);
    else
        mma_gemm_k<false, false, false><<<g, 256, SMTOT_>>>(M, N, K, Ah, Al, Bh, Bl, nullptr, nullptr, C);
}

extern "C" void kernel_launch(void* const* d_in, const int* in_sizes, int n_in,
                              void* d_out, int out_size)
{
    const int*   idx   = (const int*)  d_in[0];
    const float* tok   = (const float*)d_in[1];
    const float* pos   = (const float*)d_in[2];
    const float* ln1g  = (const float*)d_in[3];
    const float* ln1b  = (const float*)d_in[4];
    const float* ln2g  = (const float*)d_in[5];
    const float* ln2b  = (const float*)d_in[6];
    const float* wq    = (const float*)d_in[7];
    const float* wk    = (const float*)d_in[8];
    const float* wv    = (const float*)d_in[9];
    const float* wo    = (const float*)d_in[10];
    const float* bo    = (const float*)d_in[11];
    const float* w1    = (const float*)d_in[12];
    const float* b1    = (const float*)d_in[13];
    const float* w2    = (const float*)d_in[14];
    const float* b2    = (const float*)d_in[15];
    const float* lnfg  = (const float*)d_in[16];
    const float* lnfb  = (const float*)d_in[17];
    const float* whead = (const float*)d_in[18];
    const float* bhead = (const float*)d_in[19];
    float* out = (float*)d_out;

    float *x, *xn, *q, *k, *v, *att, *hb;
    __nv_bfloat16 *ah, *al, *wh, *wl;
    cudaGetSymbolAddress((void**)&x,   g_x);
    cudaGetSymbolAddress((void**)&xn,  g_xn);
    cudaGetSymbolAddress((void**)&q,   g_q);
    cudaGetSymbolAddress((void**)&k,   g_k);
    cudaGetSymbolAddress((void**)&v,   g_v);
    cudaGetSymbolAddress((void**)&att, g_att);
    cudaGetSymbolAddress((void**)&hb,  g_h);
    cudaGetSymbolAddress((void**)&ah,  g_ah);
    cudaGetSymbolAddress((void**)&al,  g_al);
    cudaGetSymbolAddress((void**)&wh,  g_wh);
    cudaGetSymbolAddress((void**)&wl,  g_wl);

    cudaFuncSetAttribute(mma_gemm_k<false,false,false>, cudaFuncAttributeMaxDynamicSharedMemorySize, SMTOT_);
    cudaFuncSetAttribute(mma_gemm_k<true,true,false>,   cudaFuncAttributeMaxDynamicSharedMemorySize, SMTOT_);
    cudaFuncSetAttribute(mma_gemm_k<true,false,true>,   cudaFuncAttributeMaxDynamicSharedMemorySize, SMTOT_);
    cudaFuncSetAttribute(mma_gemm_k<true,false,false>,  cudaFuncAttributeMaxDynamicSharedMemorySize, SMTOT_);

    // ---- weight transpose + hi/lo split ----
    dim3 tb(32, 8);
    for (int l = 0; l < L_; l++) {
        size_t base = (size_t)l * PER_L_;
        wtrans_k<<<dim3(D_/32, D_/32), tb>>>(wq + (size_t)l*DD_, wh + base,         wl + base,         D_, D_);
        wtrans_k<<<dim3(D_/32, D_/32), tb>>>(wk + (size_t)l*DD_, wh + base + DD_,   wl + base + DD_,   D_, D_);
        wtrans_k<<<dim3(D_/32, D_/32), tb>>>(wv + (size_t)l*DD_, wh + base + 2*DD_, wl + base + 2*DD_, D_, D_);
        wtrans_k<<<dim3(D_/32, D_/32), tb>>>(wo + (size_t)l*DD_, wh + base + 3*DD_, wl + base + 3*DD_, D_, D_);
        wtrans_k<<<dim3(DFF_/32, D_/32), tb>>>(w1 + (size_t)l*D_*DFF_, wh + base + 4*DD_, wl + base + 4*DD_, D_, DFF_);
        wtrans_k<<<dim3(D_/32, DFF_/32), tb>>>(w2 + (size_t)l*D_*DFF_, wh + base + 4*DD_ + (size_t)D_*DFF_,
                                               wl + base + 4*DD_ + (size_t)D_*DFF_, DFF_, D_);
    }
    size_t hoff = 4 * PER_L_;
    wtrans_k<<<dim3(V_/32, D_/32), tb>>>(whead, wh + hoff, wl + hoff, D_, V_);

    const int n4D = M_ * D_ / 4, n4F = M_ * DFF_ / 4;
    dim3 blk(256);

    embed_k<<<M_, blk>>>(idx, (const float4*)tok, (const float4*)pos, (float4*)x);

    for (int l = 0; l < L_; l++) {
        size_t base = (size_t)l * PER_L_;

        layernorm_k<<<M_, blk>>>((const float4*)x, (const float4*)(ln1g + l * D_),
                                 (const float4*)(ln1b + l * D_), (float4*)xn);
        split_k<<<(n4D + 255)/256, blk>>>((const float4*)xn, (__nv_bfloat162*)ah, (__nv_bfloat162*)al, n4D);

        gemm_launch(M_, D_, D_, ah, al, wh + base,         wl + base,         nullptr, nullptr, q, 0,0,0);
        gemm_launch(M_, D_, D_, ah, al, wh + base + DD_,   wl + base + DD_,   nullptr, nullptr, k, 0,0,0);
        gemm_launch(M_, D_, D_, ah, al, wh + base + 2*DD_, wl + base + 2*DD_, nullptr, nullptr, v, 0,0,0);

        attention2_k<<<dim3(S_ / QT_, H_, B_), 256>>>(q, k, v, att);

        split_k<<<(n4D + 255)/256, blk>>>((const float4*)att, (__nv_bfloat162*)ah, (__nv_bfloat162*)al, n4D);
        // x = xn + att @ wo + bo
        gemm_launch(M_, D_, D_, ah, al, wh + base + 3*DD_, wl + base + 3*DD_,
                    bo + l * D_, xn, x, 1,1,0);

        layernorm_k<<<M_, blk>>>((const float4*)x, (const float4*)(ln2g + l * D_),
                                 (const float4*)(ln2b + l * D_), (float4*)xn);
        split_k<<<(n4D + 255)/256, blk>>>((const float4*)xn, (__nv_bfloat162*)ah, (__nv_bfloat162*)al, n4D);

        // h = relu(xn @ w1 + b1)
        gemm_launch(M_, DFF_, D_, ah, al, wh + base + 4*DD_, wl + base + 4*DD_,
                    b1 + (size_t)l * DFF_, nullptr, hb, 1,0,1);

        split_k<<<(n4F + 255)/256, blk>>>((const float4*)hb, (__nv_bfloat162*)ah, (__nv_bfloat162*)al, n4F);
        // x = xn + h @ w2 + b2
        gemm_launch(M_, D_, DFF_, ah, al, wh + base + 4*DD_ + (size_t)D_*DFF_,
                    wl + base + 4*DD_ + (size_t)D_*DFF_, b2 + l * D_, xn, x, 1,1,0);
    }

    layernorm_k<<<M_, blk>>>((const float4*)x, (const float4*)lnfg,
                             (const float4*)lnfb, (float4*)xn);
    split_k<<<(n4D + 255)/256, blk>>>((const float4*)xn, (__nv_bfloat162*)ah, (__nv_bfloat162*)al, n4D);

    // logits = xn @ w_head + b_head
    gemm_launch(M_, V_, D_, ah, al, wh + hoff, wl + hoff, bhead, nullptr, out, 1,0,0);
}

// round 5
// speedup vs baseline: 5.0886x; 1.0139x over previous
#include <cuda_runtime.h>
#include <cuda_bf16.h>
#include <cstdint>
#include <math.h>

// ---------------------------------------------------------------------------
// MinGPT forward.  B=4, S=1024, D=1024, H=16, HS=64, L=4, DFF=4096, V=32000.
// Round 5: mma.sync bf16 hi/lo GEMM with trans-ldmatrix B (no weight
// transpose), producer-fused bf16 splits, fragment double buffering.
// ---------------------------------------------------------------------------

#define B_  4
#define S_  1024
#define D_  1024
#define H_  16
#define HS_ 64
#define L_  4
#define DFF_ 4096
#define V_  32000
#define M_  (B_ * S_)
#define EPS_ 1e-5f
#define SCALE_ 0.03125f        // D^-0.5 = 1/32 (reference uses d_model)

// ------------------------- scratch -----------------------------------------
__device__ float g_x  [M_ * D_];
__device__ float g_xn [M_ * D_];
__device__ float g_q  [M_ * D_];
__device__ float g_k  [M_ * D_];
__device__ float g_v  [M_ * D_];

// activation hi/lo splits
__device__ __align__(16) __nv_bfloat16 g_ah[M_ * D_];
__device__ __align__(16) __nv_bfloat16 g_al[M_ * D_];
__device__ __align__(16) __nv_bfloat16 g_hh[M_ * DFF_];
__device__ __align__(16) __nv_bfloat16 g_hl[M_ * DFF_];

// weight hi/lo splits, SAME [K,N] layout as inputs, packed:
// wq:0  wk:4DD  wv:8DD  wo:12DD  w1:16DD  w2:32DD  whead:48DD
#define DD_      ((size_t)D_ * D_)
#define WQ_OFF_  ((size_t)0)
#define WK_OFF_  (4 * DD_)
#define WV_OFF_  (8 * DD_)
#define WO_OFF_  (12 * DD_)
#define W1_OFF_  (16 * DD_)
#define W2_OFF_  (32 * DD_)
#define WH_OFF_  (48 * DD_)
#define WT_TOT_  (48 * DD_ + (size_t)D_ * V_)
__device__ __align__(16) __nv_bfloat16 g_wh[WT_TOT_];
__device__ __align__(16) __nv_bfloat16 g_wl[WT_TOT_];

// ------------------------- PTX helpers --------------------------------------
__device__ __forceinline__ uint32_t smem_u32(const void* p) {
    uint32_t a;
    asm("{ .reg .u64 t; cvta.to.shared.u64 t, %1; cvt.u32.u64 %0, t; }"
        : "=r"(a) : "l"(p));
    return a;
}
#define CP16(dst, src) \
    asm volatile("cp.async.cg.shared.global [%0], [%1], 16;" :: "r"(dst), "l"(src))
#define CPCOMMIT() asm volatile("cp.async.commit_group;" ::: "memory")
#define CPWAIT0()  asm volatile("cp.async.wait_group 0;" ::: "memory")
#define CPWAIT1()  asm volatile("cp.async.wait_group 1;" ::: "memory")

__device__ __forceinline__ void ldsm4(uint32_t* r, uint32_t addr) {
    asm volatile("ldmatrix.sync.aligned.m8n8.x4.shared.b16 {%0,%1,%2,%3}, [%4];"
        : "=r"(r[0]), "=r"(r[1]), "=r"(r[2]), "=r"(r[3]) : "r"(addr));
}
__device__ __forceinline__ void ldsm2t(uint32_t* r, uint32_t addr) {
    asm volatile("ldmatrix.sync.aligned.m8n8.x2.trans.shared.b16 {%0,%1}, [%2];"
        : "=r"(r[0]), "=r"(r[1]) : "r"(addr));
}
__device__ __forceinline__ void mma16816(float* d, const uint32_t* a, const uint32_t* b) {
    asm volatile(
        "mma.sync.aligned.m16n8k16.row.col.f32.bf16.bf16.f32 "
        "{%0,%1,%2,%3}, {%4,%5,%6,%7}, {%8,%9}, {%0,%1,%2,%3};"
        : "+f"(d[0]), "+f"(d[1]), "+f"(d[2]), "+f"(d[3])
        : "r"(a[0]), "r"(a[1]), "r"(a[2]), "r"(a[3]), "r"(b[0]), "r"(b[1]));
}

// ------------------------- embedding ----------------------------------------
__global__ __launch_bounds__(256) void embed_k(
    const int* __restrict__ idx, const float4* __restrict__ tok,
    const float4* __restrict__ pos, float4* __restrict__ x)
{
    int row = blockIdx.x;
    int s   = row & (S_ - 1);
    int t   = idx[row];
    int c   = threadIdx.x;
    float4 tv = tok[(size_t)t * (D_ / 4) + c];
    float4 pv = pos[(size_t)s * (D_ / 4) + c];
    float4 o;
    o.x = tv.x + pv.x; o.y = tv.y + pv.y; o.z = tv.z + pv.z; o.w = tv.w + pv.w;
    x[(size_t)row * (D_ / 4) + c] = o;
}

// ------------------------- layer norm + fused split --------------------------
__global__ __launch_bounds__(256) void layernorm_k(
    const float4* __restrict__ x, const float4* __restrict__ g,
    const float4* __restrict__ bb, float4* __restrict__ y,
    __nv_bfloat162* __restrict__ oh, __nv_bfloat162* __restrict__ ol)
{
    int row = blockIdx.x;
    int tid = threadIdx.x;
    __shared__ float red[256];

    float4 xv = x[(size_t)row * 256 + tid];
    float s = xv.x + xv.y + xv.z + xv.w;
    red[tid] = s; __syncthreads();
    #pragma unroll
    for (int st = 128; st > 0; st >>= 1) {
        if (tid < st) red[tid] += red[tid + st];
        __syncthreads();
    }
    float mu = red[0] * (1.0f / D_);
    __syncthreads();

    float dx = xv.x - mu, dy = xv.y - mu, dz = xv.z - mu, dw = xv.w - mu;
    float s2 = dx * dx + dy * dy + dz * dz + dw * dw;
    red[tid] = s2; __syncthreads();
    #pragma unroll
    for (int st = 128; st > 0; st >>= 1) {
        if (tid < st) red[tid] += red[tid + st];
        __syncthreads();
    }
    float inv = rsqrtf(red[0] * (1.0f / D_) + EPS_);

    float4 gv = g[tid], bv = bb[tid];
    float4 o;
    o.x = dx * inv * gv.x + bv.x;
    o.y = dy * inv * gv.y + bv.y;
    o.z = dz * inv * gv.z + bv.z;
    o.w = dw * inv * gv.w + bv.w;
    size_t i = (size_t)row * 256 + tid;
    y[i] = o;

    __nv_bfloat16 hx = __float2bfloat16_rn(o.x), hy = __float2bfloat16_rn(o.y);
    __nv_bfloat16 hz = __float2bfloat16_rn(o.z), hw = __float2bfloat16_rn(o.w);
    __nv_bfloat162 h0; h0.x = hx; h0.y = hy;
    __nv_bfloat162 h1; h1.x = hz; h1.y = hw;
    __nv_bfloat162 l0, l1;
    l0.x = __float2bfloat16_rn(o.x - __bfloat162float(hx));
    l0.y = __float2bfloat16_rn(o.y - __bfloat162float(hy));
    l1.x = __float2bfloat16_rn(o.z - __bfloat162float(hz));
    l1.y = __float2bfloat16_rn(o.w - __bfloat162float(hw));
    oh[2 * i] = h0; oh[2 * i + 1] = h1;
    ol[2 * i] = l0; ol[2 * i + 1] = l1;
}

// ------------------------- streaming fp32 -> bf16 hi/lo split ----------------
__global__ __launch_bounds__(256) void split_k(
    const float4* __restrict__ x, __nv_bfloat162* __restrict__ h,
    __nv_bfloat162* __restrict__ l, int n4)
{
    int i = blockIdx.x * 256 + threadIdx.x;
    if (i >= n4) return;
    float4 v = x[i];
    __nv_bfloat16 hx = __float2bfloat16_rn(v.x);
    __nv_bfloat16 hy = __float2bfloat16_rn(v.y);
    __nv_bfloat16 hz = __float2bfloat16_rn(v.z);
    __nv_bfloat16 hw = __float2bfloat16_rn(v.w);
    __nv_bfloat162 h0; h0.x = hx; h0.y = hy;
    __nv_bfloat162 h1; h1.x = hz; h1.y = hw;
    __nv_bfloat162 l0, l1;
    l0.x = __float2bfloat16_rn(v.x - __bfloat162float(hx));
    l0.y = __float2bfloat16_rn(v.y - __bfloat162float(hy));
    l1.x = __float2bfloat16_rn(v.z - __bfloat162float(hz));
    l1.y = __float2bfloat16_rn(v.w - __bfloat162float(hw));
    h[2 * i] = h0; h[2 * i + 1] = h1;
    l[2 * i] = l0; l[2 * i + 1] = l1;
}

// ------------------------- mma.sync GEMM ------------------------------------
// C[M,N] = (Ah+Al)[M,K] @ (Bh+Bl)[K,N]  (+bias)(+res)(relu)(splitout)
// A: bf16 [M,K] row-major; B: bf16 [K,N] row-major (original weight layout).
// CTA 128x128, BK=64, 8 warps = 2(M) x 4(N), warp tile 64x32,
// double-buffered cp.async, double-buffered register fragments.
#define TILEB_ 16384                       // one 16 KB tile
#define BUFB_  (4 * TILEB_)                // Ah,Al,Bh,Bl
#define SMTOT_ (2 * BUFB_)                 // 128 KB

template<bool BIAS, bool RES, bool RELU, bool OSPLIT>
__global__ __launch_bounds__(256) void mma_gemm_k(
    int M, int N, int K,
    const __nv_bfloat16* __restrict__ Ah, const __nv_bfloat16* __restrict__ Al,
    const __nv_bfloat16* __restrict__ Bh, const __nv_bfloat16* __restrict__ Bl,
    const float* __restrict__ bias, const float* __restrict__ res,
    float* __restrict__ C,
    __nv_bfloat162* __restrict__ Oh, __nv_bfloat162* __restrict__ Ol)
{
    extern __shared__ char smem[];
    const uint32_t sb = smem_u32(smem);
    const int tid = threadIdx.x, wid = tid >> 5, lane = tid & 31;
    const int mb = blockIdx.x, nb = blockIdx.y;
    const size_t ar0 = (size_t)mb * 128, bc0 = (size_t)nb * 128;
    const int wm = (wid >> 2) * 64, wn = (wid & 3) * 32;

    float acc[4][4][4];
    #pragma unroll
    for (int i = 0; i < 4; i++)
        #pragma unroll
        for (int j = 0; j < 4; j++)
            #pragma unroll
            for (int e = 0; e < 4; e++) acc[i][j][e] = 0.0f;

    const int nch = K >> 6;

    auto fill = [&](int buf, int c) {
        const size_t kof = (size_t)c << 6;
        const uint32_t bb = sb + buf * BUFB_;
        // A tiles: 128 rows x 64 bf16 (128B rows, SW128)
        #pragma unroll
        for (int i = 0; i < 4; i++) {
            int id = tid + 256 * i;          // 0..1023
            int r  = id >> 3;
            int cx = id & 7;
            uint32_t so = (uint32_t)(r * 128 + cx * 16);
            so ^= (so >> 3) & 0x70;
            size_t ai = (ar0 + r) * (size_t)K + kof + cx * 8;
            CP16(bb + 0 * TILEB_ + so, Ah + ai);
            CP16(bb + 1 * TILEB_ + so, Al + ai);
        }
        // B tiles: 64 k-rows x 128 n (256B rows, chunk^k swizzle)
        #pragma unroll
        for (int i = 0; i < 4; i++) {
            int id = tid + 256 * i;          // 0..1023
            int kr = id >> 4;                // 0..63
            int cx = id & 15;                // 16B chunk
            uint32_t so = (uint32_t)(kr * 256 + ((cx ^ (kr & 15)) * 16));
            size_t bi = (kof + kr) * (size_t)N + bc0 + cx * 8;
            CP16(bb + 2 * TILEB_ + so, Bh + bi);
            CP16(bb + 3 * TILEB_ + so, Bl + bi);
        }
    };

    fill(0, 0); CPCOMMIT();

    // fragment double buffers
    uint32_t fa_h[2][4][4], fa_l[2][4][4], fb_h[2][4][2], fb_l[2][4][2];

    const int arow = wm + (lane & 15);
    const int akb  = (lane >> 4) * 16;
    const int krl  = lane & 15;
    const int cbas = wn >> 3;

    auto ldfrag = [&](uint32_t base, int ks, int s) {
        #pragma unroll
        for (int i = 0; i < 4; i++) {
            uint32_t so = (uint32_t)((arow + i * 16) * 128 + ks * 32 + akb);
            so ^= (so >> 3) & 0x70;
            ldsm4(fa_h[s][i], base + 0 * TILEB_ + so);
            ldsm4(fa_l[s][i], base + 1 * TILEB_ + so);
        }
        const uint32_t krow = (uint32_t)(ks * 16 + krl);
        #pragma unroll
        for (int j = 0; j < 4; j++) {
            uint32_t so = krow * 256 + (((cbas + j) ^ krl) * 16);
            ldsm2t(fb_h[s][j], base + 2 * TILEB_ + so);
            ldsm2t(fb_l[s][j], base + 3 * TILEB_ + so);
        }
    };

    for (int c = 0; c < nch; c++) {
        if (c + 1 < nch) { fill((c + 1) & 1, c + 1); CPCOMMIT(); CPWAIT1(); }
        else             { CPWAIT0(); }
        __syncthreads();

        const uint32_t base = sb + (c & 1) * BUFB_;
        ldfrag(base, 0, 0);
        #pragma unroll
        for (int ks = 0; ks < 4; ks++) {
            if (ks < 3) ldfrag(base, ks + 1, (ks + 1) & 1);
            const int s = ks & 1;
            #pragma unroll
            for (int i = 0; i < 4; i++)
                #pragma unroll
                for (int j = 0; j < 4; j++) {
                    mma16816(acc[i][j], fa_h[s][i], fb_h[s][j]);
                    mma16816(acc[i][j], fa_l[s][i], fb_h[s][j]);
                    mma16816(acc[i][j], fa_h[s][i], fb_l[s][j]);
                }
        }
        __syncthreads();
    }

    // ---- epilogue ----
    const int g  = lane >> 2, tg = lane & 3;
    const size_t row0 = ar0 + wm, col0 = bc0 + wn;
    #pragma unroll
    for (int i = 0; i < 4; i++) {
        #pragma unroll
        for (int j = 0; j < 4; j++) {
            size_t col = col0 + j * 8 + tg * 2;
            float bx = 0.0f, by = 0.0f;
            if (BIAS) { bx = bias[col]; by = bias[col + 1]; }
            #pragma unroll
            for (int half = 0; half < 2; half++) {
                size_t row = row0 + i * 16 + g + half * 8;
                float vx = acc[i][j][2 * half + 0] + bx;
                float vy = acc[i][j][2 * half + 1] + by;
                size_t gi = row * (size_t)N + col;
                if (RES) { vx += res[gi]; vy += res[gi + 1]; }
                if (RELU) { vx = fmaxf(vx, 0.0f); vy = fmaxf(vy, 0.0f); }
                if (OSPLIT) {
                    __nv_bfloat16 hx = __float2bfloat16_rn(vx);
                    __nv_bfloat16 hy = __float2bfloat16_rn(vy);
                    __nv_bfloat162 hp; hp.x = hx; hp.y = hy;
                    __nv_bfloat162 lp;
                    lp.x = __float2bfloat16_rn(vx - __bfloat162float(hx));
                    lp.y = __float2bfloat16_rn(vy - __bfloat162float(hy));
                    Oh[gi >> 1] = hp;
                    Ol[gi >> 1] = lp;
                } else {
                    float2 o; o.x = vx; o.y = vy;
                    *(float2*)(C + gi) = o;
                }
            }
        }
    }
}

// ------------------------- query-tiled causal attention ---------------------
// writes bf16 hi/lo split of the output directly.
#define QT_   8
#define SPAD_ 1032
__global__ __launch_bounds__(256) void attention2_k(
    const float* __restrict__ q, const float* __restrict__ k,
    const float* __restrict__ v,
    __nv_bfloat16* __restrict__ oh, __nv_bfloat16* __restrict__ ol)
{
    int qt = blockIdx.x, h = blockIdx.y, b = blockIdx.z;
    int q0 = qt * QT_;
    int nmax = q0 + QT_;
    int tid = threadIdx.x;

    __shared__ float S[QT_][SPAD_];
    __shared__ float Rinv[QT_];

    {
        int qi = tid & 7;
        int jg = tid >> 3;
        const float* qp = q + (((size_t)b * S_ + q0 + qi) * H_ + h) * HS_;
        float4 qr[16];
        #pragma unroll
        for (int d = 0; d < 16; d++) qr[d] = *(const float4*)(qp + 4 * d);
        int nq = q0 + qi + 1;
        for (int j = jg; j < nq; j += 32) {
            const float* kp = k + (((size_t)b * S_ + j) * H_ + h) * HS_;
            float dot = 0.0f;
            #pragma unroll
            for (int d = 0; d < 16; d++) {
                float4 kk = *(const float4*)(kp + 4 * d);
                dot += kk.x * qr[d].x + kk.y * qr[d].y + kk.z * qr[d].z + kk.w * qr[d].w;
            }
            S[qi][j] = dot * SCALE_;
        }
    }
    __syncthreads();

    {
        int w = tid >> 5, l = tid & 31;
        int nq = q0 + w + 1;
        float m = -1e30f;
        for (int j = l; j < nq; j += 32) m = fmaxf(m, S[w][j]);
        #pragma unroll
        for (int st = 16; st > 0; st >>= 1)
            m = fmaxf(m, __shfl_xor_sync(0xffffffff, m, st));
        float sum = 0.0f;
        for (int j = l; j < nq; j += 32) {
            float e = __expf(S[w][j] - m);
            S[w][j] = e;
            sum += e;
        }
        #pragma unroll
        for (int st = 16; st > 0; st >>= 1)
            sum += __shfl_xor_sync(0xffffffff, sum, st);
        for (int j = nq + l; j < nmax; j += 32) S[w][j] = 0.0f;
        if (l == 0) Rinv[w] = 1.0f / sum;
    }
    __syncthreads();

    float acc[QT_][4];
    {
        int d4 = tid & 15;
        int jg = tid >> 4;
        #pragma unroll
        for (int qi = 0; qi < QT_; qi++)
            #pragma unroll
            for (int cc = 0; cc < 4; cc++) acc[qi][cc] = 0.0f;
        for (int j = jg; j < nmax; j += 16) {
            float4 vv = *(const float4*)(v + (((size_t)b * S_ + j) * H_ + h) * HS_ + d4 * 4);
            #pragma unroll
            for (int qi = 0; qi < QT_; qi++) {
                float p = S[qi][j];
                acc[qi][0] += p * vv.x; acc[qi][1] += p * vv.y;
                acc[qi][2] += p * vv.z; acc[qi][3] += p * vv.w;
            }
        }
    }
    __syncthreads();
    {
        int d4 = tid & 15;
        int jg = tid >> 4;
        float* scratch = &S[0][0];
        #pragma unroll
        for (int qi = 0; qi < QT_; qi++)
            #pragma unroll
            for (int cc = 0; cc < 4; cc++)
                scratch[jg * 512 + qi * 64 + d4 * 4 + cc] = acc[qi][cc];
    }
    __syncthreads();
    {
        const float* scratch = &S[0][0];
        #pragma unroll
        for (int e = tid; e < 512; e += 256) {
            int qi = e >> 6, d = e & 63;
            float sum = 0.0f;
            #pragma unroll
            for (int jg = 0; jg < 16; jg++) sum += scratch[jg * 512 + qi * 64 + d];
            float val = sum * Rinv[qi];
            size_t gi = (((size_t)b * S_ + q0 + qi) * H_ + h) * HS_ + d;
            __nv_bfloat16 hv = __float2bfloat16_rn(val);
            oh[gi] = hv;
            ol[gi] = __float2bfloat16_rn(val - __bfloat162float(hv));
        }
    }
}

// ------------------------- driver -------------------------------------------
extern "C" void kernel_launch(void* const* d_in, const int* in_sizes, int n_in,
                              void* d_out, int out_size)
{
    const int*   idx   = (const int*)  d_in[0];
    const float* tok   = (const float*)d_in[1];
    const float* pos   = (const float*)d_in[2];
    const float* ln1g  = (const float*)d_in[3];
    const float* ln1b  = (const float*)d_in[4];
    const float* ln2g  = (const float*)d_in[5];
    const float* ln2b  = (const float*)d_in[6];
    const float* wq    = (const float*)d_in[7];
    const float* wk    = (const float*)d_in[8];
    const float* wv    = (const float*)d_in[9];
    const float* wo    = (const float*)d_in[10];
    const float* bo    = (const float*)d_in[11];
    const float* w1    = (const float*)d_in[12];
    const float* b1    = (const float*)d_in[13];
    const float* w2    = (const float*)d_in[14];
    const float* b2    = (const float*)d_in[15];
    const float* lnfg  = (const float*)d_in[16];
    const float* lnfb  = (const float*)d_in[17];
    const float* whead = (const float*)d_in[18];
    const float* bhead = (const float*)d_in[19];
    float* out = (float*)d_out;

    float *x, *xn, *q, *k, *v;
    __nv_bfloat16 *ah, *al, *hh, *hl, *wh, *wl;
    cudaGetSymbolAddress((void**)&x,  g_x);
    cudaGetSymbolAddress((void**)&xn, g_xn);
    cudaGetSymbolAddress((void**)&q,  g_q);
    cudaGetSymbolAddress((void**)&k,  g_k);
    cudaGetSymbolAddress((void**)&v,  g_v);
    cudaGetSymbolAddress((void**)&ah, g_ah);
    cudaGetSymbolAddress((void**)&al, g_al);
    cudaGetSymbolAddress((void**)&hh, g_hh);
    cudaGetSymbolAddress((void**)&hl, g_hl);
    cudaGetSymbolAddress((void**)&wh, g_wh);
    cudaGetSymbolAddress((void**)&wl, g_wl);

    cudaFuncSetAttribute(mma_gemm_k<false,false,false,false>, cudaFuncAttributeMaxDynamicSharedMemorySize, SMTOT_);
    cudaFuncSetAttribute(mma_gemm_k<true,true,false,false>,   cudaFuncAttributeMaxDynamicSharedMemorySize, SMTOT_);
    cudaFuncSetAttribute(mma_gemm_k<true,false,true,true>,    cudaFuncAttributeMaxDynamicSharedMemorySize, SMTOT_);
    cudaFuncSetAttribute(mma_gemm_k<true,false,false,false>,  cudaFuncAttributeMaxDynamicSharedMemorySize, SMTOT_);

    dim3 blk(256);

    // ---- weight split (layout-preserving, fully coalesced) ----
    {
        int nQ = (int)(4 * DD_ / 4);          // per QKV/O tensor (all layers)
        int nF = (int)(16 * DD_ / 4);         // w1 / w2
        int nH = (int)((size_t)D_ * V_ / 4);  // head
        split_k<<<(nQ + 255)/256, blk>>>((const float4*)wq, (__nv_bfloat162*)(wh + WQ_OFF_), (__nv_bfloat162*)(wl + WQ_OFF_), nQ);
        split_k<<<(nQ + 255)/256, blk>>>((const float4*)wk, (__nv_bfloat162*)(wh + WK_OFF_), (__nv_bfloat162*)(wl + WK_OFF_), nQ);
        split_k<<<(nQ + 255)/256, blk>>>((const float4*)wv, (__nv_bfloat162*)(wh + WV_OFF_), (__nv_bfloat162*)(wl + WV_OFF_), nQ);
        split_k<<<(nQ + 255)/256, blk>>>((const float4*)wo, (__nv_bfloat162*)(wh + WO_OFF_), (__nv_bfloat162*)(wl + WO_OFF_), nQ);
        split_k<<<(nF + 255)/256, blk>>>((const float4*)w1, (__nv_bfloat162*)(wh + W1_OFF_), (__nv_bfloat162*)(wl + W1_OFF_), nF);
        split_k<<<(nF + 255)/256, blk>>>((const float4*)w2, (__nv_bfloat162*)(wh + W2_OFF_), (__nv_bfloat162*)(wl + W2_OFF_), nF);
        split_k<<<(nH + 255)/256, blk>>>((const float4*)whead, (__nv_bfloat162*)(wh + WH_OFF_), (__nv_bfloat162*)(wl + WH_OFF_), nH);
    }

    embed_k<<<M_, blk>>>(idx, (const float4*)tok, (const float4*)pos, (float4*)x);

    for (int l = 0; l < L_; l++) {
        size_t oq = WQ_OFF_ + (size_t)l * DD_;
        size_t ok = WK_OFF_ + (size_t)l * DD_;
        size_t ov = WV_OFF_ + (size_t)l * DD_;
        size_t oo = WO_OFF_ + (size_t)l * DD_;
        size_t o1 = W1_OFF_ + (size_t)l * 4 * DD_;
        size_t o2 = W2_OFF_ + (size_t)l * 4 * DD_;

        layernorm_k<<<M_, blk>>>((const float4*)x, (const float4*)(ln1g + l * D_),
                                 (const float4*)(ln1b + l * D_), (float4*)xn,
                                 (__nv_bfloat162*)ah, (__nv_bfloat162*)al);

        dim3 gQ(M_ / 128, D_ / 128);
        mma_gemm_k<false,false,false,false><<<gQ, blk, SMTOT_>>>(M_, D_, D_,
            ah, al, wh + oq, wl + oq, nullptr, nullptr, q, nullptr, nullptr);
        mma_gemm_k<false,false,false,false><<<gQ, blk, SMTOT_>>>(M_, D_, D_,
            ah, al, wh + ok, wl + ok, nullptr, nullptr, k, nullptr, nullptr);
        mma_gemm_k<false,false,false,false><<<gQ, blk, SMTOT_>>>(M_, D_, D_,
            ah, al, wh + ov, wl + ov, nullptr, nullptr, v, nullptr, nullptr);

        attention2_k<<<dim3(S_ / QT_, H_, B_), 256>>>(q, k, v, ah, al);

        // x = xn + att @ wo + bo
        mma_gemm_k<true,true,false,false><<<gQ, blk, SMTOT_>>>(M_, D_, D_,
            ah, al, wh + oo, wl + oo, bo + l * D_, xn, x, nullptr, nullptr);

        layernorm_k<<<M_, blk>>>((const float4*)x, (const float4*)(ln2g + l * D_),
                                 (const float4*)(ln2b + l * D_), (float4*)xn,
                                 (__nv_bfloat162*)ah, (__nv_bfloat162*)al);

        // h = relu(xn @ w1 + b1)  -> bf16 hi/lo directly
        mma_gemm_k<true,false,true,true><<<dim3(M_/128, DFF_/128), blk, SMTOT_>>>(
            M_, DFF_, D_, ah, al, wh + o1, wl + o1,
            b1 + (size_t)l * DFF_, nullptr, nullptr,
            (__nv_bfloat162*)hh, (__nv_bfloat162*)hl);

        // x = xn + h @ w2 + b2
        mma_gemm_k<true,true,false,false><<<dim3(M_/128, D_/128), blk, SMTOT_>>>(
            M_, D_, DFF_, hh, hl, wh + o2, wl + o2,
            b2 + l * D_, xn, x, nullptr, nullptr);
    }

    layernorm_k<<<M_, blk>>>((const float4*)x, (const float4*)lnfg,
                             (const float4*)lnfb, (float4*)xn,
                             (__nv_bfloat162*)ah, (__nv_bfloat162*)al);

    // logits = xn @ w_head + b_head
    mma_gemm_k<true,false,false,false><<<dim3(M_/128, V_/128), blk, SMTOT_>>>(
        M_, V_, D_, ah, al, wh + WH_OFF_, wl + WH_OFF_,
        bhead, nullptr, out, nullptr, nullptr);
}

// round 6
// speedup vs baseline: 5.1293x; 1.0080x over previous
#include <cuda_runtime.h>
#include <cuda_bf16.h>
#include <cstdint>
#include <math.h>

// ---------------------------------------------------------------------------
// MinGPT forward.  B=4, S=1024, D=1024, H=16, HS=64, L=4, DFF=4096, V=32000.
// Round 6: reorder split-product MMAs (break acc RAW chains) + fused QKV
// launch via gridDim.z.
// ---------------------------------------------------------------------------

#define B_  4
#define S_  1024
#define D_  1024
#define H_  16
#define HS_ 64
#define L_  4
#define DFF_ 4096
#define V_  32000
#define M_  (B_ * S_)
#define MD_ ((size_t)M_ * D_)
#define EPS_ 1e-5f
#define SCALE_ 0.03125f        // D^-0.5 = 1/32 (reference uses d_model)

// ------------------------- scratch -----------------------------------------
__device__ float g_x  [M_ * D_];
__device__ float g_xn [M_ * D_];
__device__ float g_qkv[3 * M_ * D_];

// activation hi/lo splits
__device__ __align__(16) __nv_bfloat16 g_ah[M_ * D_];
__device__ __align__(16) __nv_bfloat16 g_al[M_ * D_];
__device__ __align__(16) __nv_bfloat16 g_hh[M_ * DFF_];
__device__ __align__(16) __nv_bfloat16 g_hl[M_ * DFF_];

// weight hi/lo splits, SAME [K,N] layout as inputs, packed:
#define DD_      ((size_t)D_ * D_)
#define WQ_OFF_  ((size_t)0)
#define WK_OFF_  (4 * DD_)
#define WV_OFF_  (8 * DD_)
#define WO_OFF_  (12 * DD_)
#define W1_OFF_  (16 * DD_)
#define W2_OFF_  (32 * DD_)
#define WH_OFF_  (48 * DD_)
#define WT_TOT_  (48 * DD_ + (size_t)D_ * V_)
__device__ __align__(16) __nv_bfloat16 g_wh[WT_TOT_];
__device__ __align__(16) __nv_bfloat16 g_wl[WT_TOT_];

// ------------------------- PTX helpers --------------------------------------
__device__ __forceinline__ uint32_t smem_u32(const void* p) {
    uint32_t a;
    asm("{ .reg .u64 t; cvta.to.shared.u64 t, %1; cvt.u32.u64 %0, t; }"
        : "=r"(a) : "l"(p));
    return a;
}
#define CP16(dst, src) \
    asm volatile("cp.async.cg.shared.global [%0], [%1], 16;" :: "r"(dst), "l"(src))
#define CPCOMMIT() asm volatile("cp.async.commit_group;" ::: "memory")
#define CPWAIT0()  asm volatile("cp.async.wait_group 0;" ::: "memory")
#define CPWAIT1()  asm volatile("cp.async.wait_group 1;" ::: "memory")

__device__ __forceinline__ void ldsm4(uint32_t* r, uint32_t addr) {
    asm volatile("ldmatrix.sync.aligned.m8n8.x4.shared.b16 {%0,%1,%2,%3}, [%4];"
        : "=r"(r[0]), "=r"(r[1]), "=r"(r[2]), "=r"(r[3]) : "r"(addr));
}
__device__ __forceinline__ void ldsm2t(uint32_t* r, uint32_t addr) {
    asm volatile("ldmatrix.sync.aligned.m8n8.x2.trans.shared.b16 {%0,%1}, [%2];"
        : "=r"(r[0]), "=r"(r[1]) : "r"(addr));
}
__device__ __forceinline__ void mma16816(float* d, const uint32_t* a, const uint32_t* b) {
    asm volatile(
        "mma.sync.aligned.m16n8k16.row.col.f32.bf16.bf16.f32 "
        "{%0,%1,%2,%3}, {%4,%5,%6,%7}, {%8,%9}, {%0,%1,%2,%3};"
        : "+f"(d[0]), "+f"(d[1]), "+f"(d[2]), "+f"(d[3])
        : "r"(a[0]), "r"(a[1]), "r"(a[2]), "r"(a[3]), "r"(b[0]), "r"(b[1]));
}

// ------------------------- embedding ----------------------------------------
__global__ __launch_bounds__(256) void embed_k(
    const int* __restrict__ idx, const float4* __restrict__ tok,
    const float4* __restrict__ pos, float4* __restrict__ x)
{
    int row = blockIdx.x;
    int s   = row & (S_ - 1);
    int t   = idx[row];
    int c   = threadIdx.x;
    float4 tv = tok[(size_t)t * (D_ / 4) + c];
    float4 pv = pos[(size_t)s * (D_ / 4) + c];
    float4 o;
    o.x = tv.x + pv.x; o.y = tv.y + pv.y; o.z = tv.z + pv.z; o.w = tv.w + pv.w;
    x[(size_t)row * (D_ / 4) + c] = o;
}

// ------------------------- layer norm + fused split --------------------------
__global__ __launch_bounds__(256) void layernorm_k(
    const float4* __restrict__ x, const float4* __restrict__ g,
    const float4* __restrict__ bb, float4* __restrict__ y,
    __nv_bfloat162* __restrict__ oh, __nv_bfloat162* __restrict__ ol)
{
    int row = blockIdx.x;
    int tid = threadIdx.x;
    __shared__ float red[256];

    float4 xv = x[(size_t)row * 256 + tid];
    float s = xv.x + xv.y + xv.z + xv.w;
    red[tid] = s; __syncthreads();
    #pragma unroll
    for (int st = 128; st > 0; st >>= 1) {
        if (tid < st) red[tid] += red[tid + st];
        __syncthreads();
    }
    float mu = red[0] * (1.0f / D_);
    __syncthreads();

    float dx = xv.x - mu, dy = xv.y - mu, dz = xv.z - mu, dw = xv.w - mu;
    float s2 = dx * dx + dy * dy + dz * dz + dw * dw;
    red[tid] = s2; __syncthreads();
    #pragma unroll
    for (int st = 128; st > 0; st >>= 1) {
        if (tid < st) red[tid] += red[tid + st];
        __syncthreads();
    }
    float inv = rsqrtf(red[0] * (1.0f / D_) + EPS_);

    float4 gv = g[tid], bv = bb[tid];
    float4 o;
    o.x = dx * inv * gv.x + bv.x;
    o.y = dy * inv * gv.y + bv.y;
    o.z = dz * inv * gv.z + bv.z;
    o.w = dw * inv * gv.w + bv.w;
    size_t i = (size_t)row * 256 + tid;
    y[i] = o;

    __nv_bfloat16 hx = __float2bfloat16_rn(o.x), hy = __float2bfloat16_rn(o.y);
    __nv_bfloat16 hz = __float2bfloat16_rn(o.z), hw = __float2bfloat16_rn(o.w);
    __nv_bfloat162 h0; h0.x = hx; h0.y = hy;
    __nv_bfloat162 h1; h1.x = hz; h1.y = hw;
    __nv_bfloat162 l0, l1;
    l0.x = __float2bfloat16_rn(o.x - __bfloat162float(hx));
    l0.y = __float2bfloat16_rn(o.y - __bfloat162float(hy));
    l1.x = __float2bfloat16_rn(o.z - __bfloat162float(hz));
    l1.y = __float2bfloat16_rn(o.w - __bfloat162float(hw));
    oh[2 * i] = h0; oh[2 * i + 1] = h1;
    ol[2 * i] = l0; ol[2 * i + 1] = l1;
}

// ------------------------- streaming fp32 -> bf16 hi/lo split ----------------
__global__ __launch_bounds__(256) void split_k(
    const float4* __restrict__ x, __nv_bfloat162* __restrict__ h,
    __nv_bfloat162* __restrict__ l, int n4)
{
    int i = blockIdx.x * 256 + threadIdx.x;
    if (i >= n4) return;
    float4 v = x[i];
    __nv_bfloat16 hx = __float2bfloat16_rn(v.x);
    __nv_bfloat16 hy = __float2bfloat16_rn(v.y);
    __nv_bfloat16 hz = __float2bfloat16_rn(v.z);
    __nv_bfloat16 hw = __float2bfloat16_rn(v.w);
    __nv_bfloat162 h0; h0.x = hx; h0.y = hy;
    __nv_bfloat162 h1; h1.x = hz; h1.y = hw;
    __nv_bfloat162 l0, l1;
    l0.x = __float2bfloat16_rn(v.x - __bfloat162float(hx));
    l0.y = __float2bfloat16_rn(v.y - __bfloat162float(hy));
    l1.x = __float2bfloat16_rn(v.z - __bfloat162float(hz));
    l1.y = __float2bfloat16_rn(v.w - __bfloat162float(hw));
    h[2 * i] = h0; h[2 * i + 1] = h1;
    l[2 * i] = l0; l[2 * i + 1] = l1;
}

// ------------------------- mma.sync GEMM ------------------------------------
// C[M,N] = (Ah+Al)[M,K] @ (Bh+Bl)[K,N]  (+bias)(+res)(relu)(splitout)
// gridDim.z selects weight/output group: B += z*bzS, C += z*czS  (fused QKV).
// CTA 128x128, BK=64, 8 warps = 2(M) x 4(N), double-buffered cp.async.
// Split products issued product-major: no back-to-back RAW on accumulators.
#define TILEB_ 16384
#define BUFB_  (4 * TILEB_)
#define SMTOT_ (2 * BUFB_)

template<bool BIAS, bool RES, bool RELU, bool OSPLIT>
__global__ __launch_bounds__(256) void mma_gemm_k(
    int M, int N, int K,
    const __nv_bfloat16* __restrict__ Ah, const __nv_bfloat16* __restrict__ Al,
    const __nv_bfloat16* __restrict__ Bh, const __nv_bfloat16* __restrict__ Bl,
    const float* __restrict__ bias, const float* __restrict__ res,
    float* __restrict__ C,
    __nv_bfloat162* __restrict__ Oh, __nv_bfloat162* __restrict__ Ol,
    size_t bzS, size_t czS)
{
    extern __shared__ char smem[];
    const uint32_t sb = smem_u32(smem);
    const int tid = threadIdx.x, wid = tid >> 5, lane = tid & 31;
    const int mb = blockIdx.x, nb = blockIdx.y;
    Bh += blockIdx.z * bzS;  Bl += blockIdx.z * bzS;
    C  += blockIdx.z * czS;
    const size_t ar0 = (size_t)mb * 128, bc0 = (size_t)nb * 128;
    const int wm = (wid >> 2) * 64, wn = (wid & 3) * 32;

    float acc[4][4][4];
    #pragma unroll
    for (int i = 0; i < 4; i++)
        #pragma unroll
        for (int j = 0; j < 4; j++)
            #pragma unroll
            for (int e = 0; e < 4; e++) acc[i][j][e] = 0.0f;

    const int nch = K >> 6;

    auto fill = [&](int buf, int c) {
        const size_t kof = (size_t)c << 6;
        const uint32_t bb = sb + buf * BUFB_;
        #pragma unroll
        for (int i = 0; i < 4; i++) {
            int id = tid + 256 * i;
            int r  = id >> 3;
            int cx = id & 7;
            uint32_t so = (uint32_t)(r * 128 + cx * 16);
            so ^= (so >> 3) & 0x70;
            size_t ai = (ar0 + r) * (size_t)K + kof + cx * 8;
            CP16(bb + 0 * TILEB_ + so, Ah + ai);
            CP16(bb + 1 * TILEB_ + so, Al + ai);
        }
        #pragma unroll
        for (int i = 0; i < 4; i++) {
            int id = tid + 256 * i;
            int kr = id >> 4;
            int cx = id & 15;
            uint32_t so = (uint32_t)(kr * 256 + ((cx ^ (kr & 15)) * 16));
            size_t bi = (kof + kr) * (size_t)N + bc0 + cx * 8;
            CP16(bb + 2 * TILEB_ + so, Bh + bi);
            CP16(bb + 3 * TILEB_ + so, Bl + bi);
        }
    };

    fill(0, 0); CPCOMMIT();

    uint32_t fa_h[4][4], fa_l[4][4], fb_h[4][2], fb_l[4][2];
    const int arow = wm + (lane & 15);
    const int akb  = (lane >> 4) * 16;
    const int krl  = lane & 15;
    const int cbas = wn >> 3;

    for (int c = 0; c < nch; c++) {
        if (c + 1 < nch) { fill((c + 1) & 1, c + 1); CPCOMMIT(); CPWAIT1(); }
        else             { CPWAIT0(); }
        __syncthreads();

        const uint32_t base = sb + (c & 1) * BUFB_;
        #pragma unroll
        for (int ks = 0; ks < 4; ks++) {
            #pragma unroll
            for (int i = 0; i < 4; i++) {
                uint32_t so = (uint32_t)((arow + i * 16) * 128 + ks * 32 + akb);
                so ^= (so >> 3) & 0x70;
                ldsm4(fa_h[i], base + 0 * TILEB_ + so);
                ldsm4(fa_l[i], base + 1 * TILEB_ + so);
            }
            const uint32_t krow = (uint32_t)(ks * 16 + krl);
            #pragma unroll
            for (int j = 0; j < 4; j++) {
                uint32_t so = krow * 256 + (((cbas + j) ^ krl) * 16);
                ldsm2t(fb_h[j], base + 2 * TILEB_ + so);
                ldsm2t(fb_l[j], base + 3 * TILEB_ + so);
            }
            // product-major: 16 independent accumulators between reuses
            #pragma unroll
            for (int i = 0; i < 4; i++)
                #pragma unroll
                for (int j = 0; j < 4; j++)
                    mma16816(acc[i][j], fa_h[i], fb_h[j]);
            #pragma unroll
            for (int i = 0; i < 4; i++)
                #pragma unroll
                for (int j = 0; j < 4; j++)
                    mma16816(acc[i][j], fa_l[i], fb_h[j]);
            #pragma unroll
            for (int i = 0; i < 4; i++)
                #pragma unroll
                for (int j = 0; j < 4; j++)
                    mma16816(acc[i][j], fa_h[i], fb_l[j]);
        }
        __syncthreads();
    }

    // ---- epilogue ----
    const int g  = lane >> 2, tg = lane & 3;
    const size_t row0 = ar0 + wm, col0 = bc0 + wn;
    #pragma unroll
    for (int i = 0; i < 4; i++) {
        #pragma unroll
        for (int j = 0; j < 4; j++) {
            size_t col = col0 + j * 8 + tg * 2;
            float bx = 0.0f, by = 0.0f;
            if (BIAS) { bx = bias[col]; by = bias[col + 1]; }
            #pragma unroll
            for (int half = 0; half < 2; half++) {
                size_t row = row0 + i * 16 + g + half * 8;
                float vx = acc[i][j][2 * half + 0] + bx;
                float vy = acc[i][j][2 * half + 1] + by;
                size_t gi = row * (size_t)N + col;
                if (RES) { vx += res[gi]; vy += res[gi + 1]; }
                if (RELU) { vx = fmaxf(vx, 0.0f); vy = fmaxf(vy, 0.0f); }
                if (OSPLIT) {
                    __nv_bfloat16 hx = __float2bfloat16_rn(vx);
                    __nv_bfloat16 hy = __float2bfloat16_rn(vy);
                    __nv_bfloat162 hp; hp.x = hx; hp.y = hy;
                    __nv_bfloat162 lp;
                    lp.x = __float2bfloat16_rn(vx - __bfloat162float(hx));
                    lp.y = __float2bfloat16_rn(vy - __bfloat162float(hy));
                    Oh[gi >> 1] = hp;
                    Ol[gi >> 1] = lp;
                } else {
                    float2 o; o.x = vx; o.y = vy;
                    *(float2*)(C + gi) = o;
                }
            }
        }
    }
}

// ------------------------- query-tiled causal attention ---------------------
#define QT_   8
#define SPAD_ 1032
__global__ __launch_bounds__(256) void attention2_k(
    const float* __restrict__ q, const float* __restrict__ k,
    const float* __restrict__ v,
    __nv_bfloat16* __restrict__ oh, __nv_bfloat16* __restrict__ ol)
{
    int qt = blockIdx.x, h = blockIdx.y, b = blockIdx.z;
    int q0 = qt * QT_;
    int nmax = q0 + QT_;
    int tid = threadIdx.x;

    __shared__ float S[QT_][SPAD_];
    __shared__ float Rinv[QT_];

    {
        int qi = tid & 7;
        int jg = tid >> 3;
        const float* qp = q + (((size_t)b * S_ + q0 + qi) * H_ + h) * HS_;
        float4 qr[16];
        #pragma unroll
        for (int d = 0; d < 16; d++) qr[d] = *(const float4*)(qp + 4 * d);
        int nq = q0 + qi + 1;
        for (int j = jg; j < nq; j += 32) {
            const float* kp = k + (((size_t)b * S_ + j) * H_ + h) * HS_;
            float dot = 0.0f;
            #pragma unroll
            for (int d = 0; d < 16; d++) {
                float4 kk = *(const float4*)(kp + 4 * d);
                dot += kk.x * qr[d].x + kk.y * qr[d].y + kk.z * qr[d].z + kk.w * qr[d].w;
            }
            S[qi][j] = dot * SCALE_;
        }
    }
    __syncthreads();

    {
        int w = tid >> 5, l = tid & 31;
        int nq = q0 + w + 1;
        float m = -1e30f;
        for (int j = l; j < nq; j += 32) m = fmaxf(m, S[w][j]);
        #pragma unroll
        for (int st = 16; st > 0; st >>= 1)
            m = fmaxf(m, __shfl_xor_sync(0xffffffff, m, st));
        float sum = 0.0f;
        for (int j = l; j < nq; j += 32) {
            float e = __expf(S[w][j] - m);
            S[w][j] = e;
            sum += e;
        }
        #pragma unroll
        for (int st = 16; st > 0; st >>= 1)
            sum += __shfl_xor_sync(0xffffffff, sum, st);
        for (int j = nq + l; j < nmax; j += 32) S[w][j] = 0.0f;
        if (l == 0) Rinv[w] = 1.0f / sum;
    }
    __syncthreads();

    float acc[QT_][4];
    {
        int d4 = tid & 15;
        int jg = tid >> 4;
        #pragma unroll
        for (int qi = 0; qi < QT_; qi++)
            #pragma unroll
            for (int cc = 0; cc < 4; cc++) acc[qi][cc] = 0.0f;
        for (int j = jg; j < nmax; j += 16) {
            float4 vv = *(const float4*)(v + (((size_t)b * S_ + j) * H_ + h) * HS_ + d4 * 4);
            #pragma unroll
            for (int qi = 0; qi < QT_; qi++) {
                float p = S[qi][j];
                acc[qi][0] += p * vv.x; acc[qi][1] += p * vv.y;
                acc[qi][2] += p * vv.z; acc[qi][3] += p * vv.w;
            }
        }
    }
    __syncthreads();
    {
        int d4 = tid & 15;
        int jg = tid >> 4;
        float* scratch = &S[0][0];
        #pragma unroll
        for (int qi = 0; qi < QT_; qi++)
            #pragma unroll
            for (int cc = 0; cc < 4; cc++)
                scratch[jg * 512 + qi * 64 + d4 * 4 + cc] = acc[qi][cc];
    }
    __syncthreads();
    {
        const float* scratch = &S[0][0];
        #pragma unroll
        for (int e = tid; e < 512; e += 256) {
            int qi = e >> 6, d = e & 63;
            float sum = 0.0f;
            #pragma unroll
            for (int jg = 0; jg < 16; jg++) sum += scratch[jg * 512 + qi * 64 + d];
            float val = sum * Rinv[qi];
            size_t gi = (((size_t)b * S_ + q0 + qi) * H_ + h) * HS_ + d;
            __nv_bfloat16 hv = __float2bfloat16_rn(val);
            oh[gi] = hv;
            ol[gi] = __float2bfloat16_rn(val - __bfloat162float(hv));
        }
    }
}

// ------------------------- driver -------------------------------------------
extern "C" void kernel_launch(void* const* d_in, const int* in_sizes, int n_in,
                              void* d_out, int out_size)
{
    const int*   idx   = (const int*)  d_in[0];
    const float* tok   = (const float*)d_in[1];
    const float* pos   = (const float*)d_in[2];
    const float* ln1g  = (const float*)d_in[3];
    const float* ln1b  = (const float*)d_in[4];
    const float* ln2g  = (const float*)d_in[5];
    const float* ln2b  = (const float*)d_in[6];
    const float* wq    = (const float*)d_in[7];
    const float* wk    = (const float*)d_in[8];
    const float* wv    = (const float*)d_in[9];
    const float* wo    = (const float*)d_in[10];
    const float* bo    = (const float*)d_in[11];
    const float* w1    = (const float*)d_in[12];
    const float* b1    = (const float*)d_in[13];
    const float* w2    = (const float*)d_in[14];
    const float* b2    = (const float*)d_in[15];
    const float* lnfg  = (const float*)d_in[16];
    const float* lnfb  = (const float*)d_in[17];
    const float* whead = (const float*)d_in[18];
    const float* bhead = (const float*)d_in[19];
    float* out = (float*)d_out;

    float *x, *xn, *qkv;
    __nv_bfloat16 *ah, *al, *hh, *hl, *wh, *wl;
    cudaGetSymbolAddress((void**)&x,   g_x);
    cudaGetSymbolAddress((void**)&xn,  g_xn);
    cudaGetSymbolAddress((void**)&qkv, g_qkv);
    cudaGetSymbolAddress((void**)&ah,  g_ah);
    cudaGetSymbolAddress((void**)&al,  g_al);
    cudaGetSymbolAddress((void**)&hh,  g_hh);
    cudaGetSymbolAddress((void**)&hl,  g_hl);
    cudaGetSymbolAddress((void**)&wh,  g_wh);
    cudaGetSymbolAddress((void**)&wl,  g_wl);

    cudaFuncSetAttribute(mma_gemm_k<false,false,false,false>, cudaFuncAttributeMaxDynamicSharedMemorySize, SMTOT_);
    cudaFuncSetAttribute(mma_gemm_k<true,true,false,false>,   cudaFuncAttributeMaxDynamicSharedMemorySize, SMTOT_);
    cudaFuncSetAttribute(mma_gemm_k<true,false,true,true>,    cudaFuncAttributeMaxDynamicSharedMemorySize, SMTOT_);
    cudaFuncSetAttribute(mma_gemm_k<true,false,false,false>,  cudaFuncAttributeMaxDynamicSharedMemorySize, SMTOT_);

    dim3 blk(256);

    // ---- weight split (layout-preserving, fully coalesced) ----
    {
        int nQ = (int)(4 * DD_ / 4);
        int nF = (int)(16 * DD_ / 4);
        int nH = (int)((size_t)D_ * V_ / 4);
        split_k<<<(nQ + 255)/256, blk>>>((const float4*)wq, (__nv_bfloat162*)(wh + WQ_OFF_), (__nv_bfloat162*)(wl + WQ_OFF_), nQ);
        split_k<<<(nQ + 255)/256, blk>>>((const float4*)wk, (__nv_bfloat162*)(wh + WK_OFF_), (__nv_bfloat162*)(wl + WK_OFF_), nQ);
        split_k<<<(nQ + 255)/256, blk>>>((const float4*)wv, (__nv_bfloat162*)(wh + WV_OFF_), (__nv_bfloat162*)(wl + WV_OFF_), nQ);
        split_k<<<(nQ + 255)/256, blk>>>((const float4*)wo, (__nv_bfloat162*)(wh + WO_OFF_), (__nv_bfloat162*)(wl + WO_OFF_), nQ);
        split_k<<<(nF + 255)/256, blk>>>((const float4*)w1, (__nv_bfloat162*)(wh + W1_OFF_), (__nv_bfloat162*)(wl + W1_OFF_), nF);
        split_k<<<(nF + 255)/256, blk>>>((const float4*)w2, (__nv_bfloat162*)(wh + W2_OFF_), (__nv_bfloat162*)(wl + W2_OFF_), nF);
        split_k<<<(nH + 255)/256, blk>>>((const float4*)whead, (__nv_bfloat162*)(wh + WH_OFF_), (__nv_bfloat162*)(wl + WH_OFF_), nH);
    }

    embed_k<<<M_, blk>>>(idx, (const float4*)tok, (const float4*)pos, (float4*)x);

    for (int l = 0; l < L_; l++) {
        size_t oq = WQ_OFF_ + (size_t)l * DD_;
        size_t oo = WO_OFF_ + (size_t)l * DD_;
        size_t o1 = W1_OFF_ + (size_t)l * 4 * DD_;
        size_t o2 = W2_OFF_ + (size_t)l * 4 * DD_;

        layernorm_k<<<M_, blk>>>((const float4*)x, (const float4*)(ln1g + l * D_),
                                 (const float4*)(ln1b + l * D_), (float4*)xn,
                                 (__nv_bfloat162*)ah, (__nv_bfloat162*)al);

        // fused QKV: z selects wq/wk/wv (stride 4*DD_) and q/k/v slab (stride MD_)
        mma_gemm_k<false,false,false,false><<<dim3(M_/128, D_/128, 3), blk, SMTOT_>>>(
            M_, D_, D_, ah, al, wh + oq, wl + oq, nullptr, nullptr, qkv,
            nullptr, nullptr, 4 * DD_, MD_);

        attention2_k<<<dim3(S_ / QT_, H_, B_), 256>>>(qkv, qkv + MD_, qkv + 2 * MD_, ah, al);

        // x = xn + att @ wo + bo
        mma_gemm_k<true,true,false,false><<<dim3(M_/128, D_/128), blk, SMTOT_>>>(
            M_, D_, D_, ah, al, wh + oo, wl + oo, bo + l * D_, xn, x,
            nullptr, nullptr, 0, 0);

        layernorm_k<<<M_, blk>>>((const float4*)x, (const float4*)(ln2g + l * D_),
                                 (const float4*)(ln2b + l * D_), (float4*)xn,
                                 (__nv_bfloat162*)ah, (__nv_bfloat162*)al);

        // h = relu(xn @ w1 + b1)  -> bf16 hi/lo directly
        mma_gemm_k<true,false,true,true><<<dim3(M_/128, DFF_/128), blk, SMTOT_>>>(
            M_, DFF_, D_, ah, al, wh + o1, wl + o1,
            b1 + (size_t)l * DFF_, nullptr, nullptr,
            (__nv_bfloat162*)hh, (__nv_bfloat162*)hl, 0, 0);

        // x = xn + h @ w2 + b2
        mma_gemm_k<true,true,false,false><<<dim3(M_/128, D_/128), blk, SMTOT_>>>(
            M_, D_, DFF_, hh, hl, wh + o2, wl + o2,
            b2 + l * D_, xn, x, nullptr, nullptr, 0, 0);
    }

    layernorm_k<<<M_, blk>>>((const float4*)x, (const float4*)lnfg,
                             (const float4*)lnfb, (float4*)xn,
                             (__nv_bfloat162*)ah, (__nv_bfloat162*)al);

    // logits = xn @ w_head + b_head
    mma_gemm_k<true,false,false,false><<<dim3(M_/128, V_/128), blk, SMTOT_>>>(
        M_, V_, D_, ah, al, wh + WH_OFF_, wl + WH_OFF_,
        bhead, nullptr, out, nullptr, nullptr, 0, 0);
}

// round 7
// speedup vs baseline: 6.2303x; 1.2146x over previous
#include <cuda_runtime.h>
#include <cuda_fp16.h>
#include <cstdint>
#include <math.h>

// ---------------------------------------------------------------------------
// MinGPT forward.  B=4, S=1024, D=1024, H=16, HS=64, L=4, DFF=4096, V=32000.
// Round 7: fp16 2-product split GEMM (A hi+lo fp16, W single fp16),
//          2 CTAs/SM, QT=16 attention.
// ---------------------------------------------------------------------------

#define B_  4
#define S_  1024
#define D_  1024
#define H_  16
#define HS_ 64
#define L_  4
#define DFF_ 4096
#define V_  32000
#define M_  (B_ * S_)
#define MD_ ((size_t)M_ * D_)
#define EPS_ 1e-5f
#define SCALE_ 0.03125f        // D^-0.5 = 1/32 (reference uses d_model)

// ------------------------- scratch -----------------------------------------
__device__ float g_x  [M_ * D_];
__device__ float g_xn [M_ * D_];
__device__ float g_qkv[3 * M_ * D_];

// activation hi/lo splits (fp16)
__device__ __align__(16) __half g_ah[M_ * D_];
__device__ __align__(16) __half g_al[M_ * D_];
__device__ __align__(16) __half g_hh[M_ * DFF_];
__device__ __align__(16) __half g_hl[M_ * DFF_];

// weights: single fp16, SAME [K,N] layout as inputs, packed
#define DD_      ((size_t)D_ * D_)
#define WQ_OFF_  ((size_t)0)
#define WK_OFF_  (4 * DD_)
#define WV_OFF_  (8 * DD_)
#define WO_OFF_  (12 * DD_)
#define W1_OFF_  (16 * DD_)
#define W2_OFF_  (32 * DD_)
#define WH_OFF_  (48 * DD_)
#define WT_TOT_  (48 * DD_ + (size_t)D_ * V_)
__device__ __align__(16) __half g_wh[WT_TOT_];

// ------------------------- PTX helpers --------------------------------------
__device__ __forceinline__ uint32_t smem_u32(const void* p) {
    uint32_t a;
    asm("{ .reg .u64 t; cvta.to.shared.u64 t, %1; cvt.u32.u64 %0, t; }"
        : "=r"(a) : "l"(p));
    return a;
}
#define CP16(dst, src) \
    asm volatile("cp.async.cg.shared.global [%0], [%1], 16;" :: "r"(dst), "l"(src))
#define CPCOMMIT() asm volatile("cp.async.commit_group;" ::: "memory")
#define CPWAIT0()  asm volatile("cp.async.wait_group 0;" ::: "memory")
#define CPWAIT1()  asm volatile("cp.async.wait_group 1;" ::: "memory")

__device__ __forceinline__ void ldsm4(uint32_t* r, uint32_t addr) {
    asm volatile("ldmatrix.sync.aligned.m8n8.x4.shared.b16 {%0,%1,%2,%3}, [%4];"
        : "=r"(r[0]), "=r"(r[1]), "=r"(r[2]), "=r"(r[3]) : "r"(addr));
}
__device__ __forceinline__ void ldsm2t(uint32_t* r, uint32_t addr) {
    asm volatile("ldmatrix.sync.aligned.m8n8.x2.trans.shared.b16 {%0,%1}, [%2];"
        : "=r"(r[0]), "=r"(r[1]) : "r"(addr));
}
__device__ __forceinline__ void mma16816(float* d, const uint32_t* a, const uint32_t* b) {
    asm volatile(
        "mma.sync.aligned.m16n8k16.row.col.f32.f16.f16.f32 "
        "{%0,%1,%2,%3}, {%4,%5,%6,%7}, {%8,%9}, {%0,%1,%2,%3};"
        : "+f"(d[0]), "+f"(d[1]), "+f"(d[2]), "+f"(d[3])
        : "r"(a[0]), "r"(a[1]), "r"(a[2]), "r"(a[3]), "r"(b[0]), "r"(b[1]));
}

// ------------------------- embedding ----------------------------------------
__global__ __launch_bounds__(256) void embed_k(
    const int* __restrict__ idx, const float4* __restrict__ tok,
    const float4* __restrict__ pos, float4* __restrict__ x)
{
    int row = blockIdx.x;
    int s   = row & (S_ - 1);
    int t   = idx[row];
    int c   = threadIdx.x;
    float4 tv = tok[(size_t)t * (D_ / 4) + c];
    float4 pv = pos[(size_t)s * (D_ / 4) + c];
    float4 o;
    o.x = tv.x + pv.x; o.y = tv.y + pv.y; o.z = tv.z + pv.z; o.w = tv.w + pv.w;
    x[(size_t)row * (D_ / 4) + c] = o;
}

// ------------------------- layer norm + fused fp16 split ---------------------
__global__ __launch_bounds__(256) void layernorm_k(
    const float4* __restrict__ x, const float4* __restrict__ g,
    const float4* __restrict__ bb, float4* __restrict__ y,
    __half2* __restrict__ oh, __half2* __restrict__ ol)
{
    int row = blockIdx.x;
    int tid = threadIdx.x;
    __shared__ float red[256];

    float4 xv = x[(size_t)row * 256 + tid];
    float s = xv.x + xv.y + xv.z + xv.w;
    red[tid] = s; __syncthreads();
    #pragma unroll
    for (int st = 128; st > 0; st >>= 1) {
        if (tid < st) red[tid] += red[tid + st];
        __syncthreads();
    }
    float mu = red[0] * (1.0f / D_);
    __syncthreads();

    float dx = xv.x - mu, dy = xv.y - mu, dz = xv.z - mu, dw = xv.w - mu;
    float s2 = dx * dx + dy * dy + dz * dz + dw * dw;
    red[tid] = s2; __syncthreads();
    #pragma unroll
    for (int st = 128; st > 0; st >>= 1) {
        if (tid < st) red[tid] += red[tid + st];
        __syncthreads();
    }
    float inv = rsqrtf(red[0] * (1.0f / D_) + EPS_);

    float4 gv = g[tid], bv = bb[tid];
    float4 o;
    o.x = dx * inv * gv.x + bv.x;
    o.y = dy * inv * gv.y + bv.y;
    o.z = dz * inv * gv.z + bv.z;
    o.w = dw * inv * gv.w + bv.w;
    size_t i = (size_t)row * 256 + tid;
    y[i] = o;

    __half hx = __float2half_rn(o.x), hy = __float2half_rn(o.y);
    __half hz = __float2half_rn(o.z), hw = __float2half_rn(o.w);
    oh[2 * i]     = __halves2half2(hx, hy);
    oh[2 * i + 1] = __halves2half2(hz, hw);
    ol[2 * i]     = __halves2half2(__float2half_rn(o.x - __half2float(hx)),
                                   __float2half_rn(o.y - __half2float(hy)));
    ol[2 * i + 1] = __halves2half2(__float2half_rn(o.z - __half2float(hz)),
                                   __float2half_rn(o.w - __half2float(hw)));
}

// ------------------------- fp32 -> single fp16 (weights) ---------------------
__global__ __launch_bounds__(256) void wsplit_k(
    const float4* __restrict__ x, __half2* __restrict__ h, int n4)
{
    int i = blockIdx.x * 256 + threadIdx.x;
    if (i >= n4) return;
    float4 v = x[i];
    h[2 * i]     = __halves2half2(__float2half_rn(v.x), __float2half_rn(v.y));
    h[2 * i + 1] = __halves2half2(__float2half_rn(v.z), __float2half_rn(v.w));
}

// ------------------------- mma.sync GEMM ------------------------------------
// C[M,N] = (Ah+Al)[M,K] @ B[K,N]  (+bias)(+res)(relu)(splitout),  fp16 in.
// gridDim.z: B += z*bzS, C += z*czS (fused QKV).
// CTA 128x128, BK=64, 8 warps = 2(M) x 4(N), double-buffered cp.async.
// 3 smem tiles/chunk (Ah, Al, B) -> 96 KB total -> 2 CTAs/SM.
#define TILEB_ 16384
#define BUFB_  (3 * TILEB_)
#define SMTOT_ (2 * BUFB_)

template<bool BIAS, bool RES, bool RELU, bool OSPLIT>
__global__ __launch_bounds__(256) void mma_gemm_k(
    int M, int N, int K,
    const __half* __restrict__ Ah, const __half* __restrict__ Al,
    const __half* __restrict__ Bw,
    const float* __restrict__ bias, const float* __restrict__ res,
    float* __restrict__ C,
    __half2* __restrict__ Oh, __half2* __restrict__ Ol,
    size_t bzS, size_t czS)
{
    extern __shared__ char smem[];
    const uint32_t sb = smem_u32(smem);
    const int tid = threadIdx.x, wid = tid >> 5, lane = tid & 31;
    const int mb = blockIdx.x, nb = blockIdx.y;
    Bw += blockIdx.z * bzS;
    C  += blockIdx.z * czS;
    const size_t ar0 = (size_t)mb * 128, bc0 = (size_t)nb * 128;
    const int wm = (wid >> 2) * 64, wn = (wid & 3) * 32;

    float acc[4][4][4];
    #pragma unroll
    for (int i = 0; i < 4; i++)
        #pragma unroll
        for (int j = 0; j < 4; j++)
            #pragma unroll
            for (int e = 0; e < 4; e++) acc[i][j][e] = 0.0f;

    const int nch = K >> 6;

    auto fill = [&](int buf, int c) {
        const size_t kof = (size_t)c << 6;
        const uint32_t bb = sb + buf * BUFB_;
        // A tiles: 128 rows x 64 fp16 (128B rows, SW128)
        #pragma unroll
        for (int i = 0; i < 4; i++) {
            int id = tid + 256 * i;
            int r  = id >> 3;
            int cx = id & 7;
            uint32_t so = (uint32_t)(r * 128 + cx * 16);
            so ^= (so >> 3) & 0x70;
            size_t ai = (ar0 + r) * (size_t)K + kof + cx * 8;
            CP16(bb + 0 * TILEB_ + so, Ah + ai);
            CP16(bb + 1 * TILEB_ + so, Al + ai);
        }
        // B tile: 64 k-rows x 128 n (256B rows, chunk^k swizzle)
        #pragma unroll
        for (int i = 0; i < 4; i++) {
            int id = tid + 256 * i;
            int kr = id >> 4;
            int cx = id & 15;
            uint32_t so = (uint32_t)(kr * 256 + ((cx ^ (kr & 15)) * 16));
            size_t bi = (kof + kr) * (size_t)N + bc0 + cx * 8;
            CP16(bb + 2 * TILEB_ + so, Bw + bi);
        }
    };

    fill(0, 0); CPCOMMIT();

    uint32_t fa_h[4][4], fa_l[4][4], fb[4][2];
    const int arow = wm + (lane & 15);
    const int akb  = (lane >> 4) * 16;
    const int krl  = lane & 15;
    const int cbas = wn >> 3;

    for (int c = 0; c < nch; c++) {
        if (c + 1 < nch) { fill((c + 1) & 1, c + 1); CPCOMMIT(); CPWAIT1(); }
        else             { CPWAIT0(); }
        __syncthreads();

        const uint32_t base = sb + (c & 1) * BUFB_;
        #pragma unroll
        for (int ks = 0; ks < 4; ks++) {
            #pragma unroll
            for (int i = 0; i < 4; i++) {
                uint32_t so = (uint32_t)((arow + i * 16) * 128 + ks * 32 + akb);
                so ^= (so >> 3) & 0x70;
                ldsm4(fa_h[i], base + 0 * TILEB_ + so);
                ldsm4(fa_l[i], base + 1 * TILEB_ + so);
            }
            const uint32_t krow = (uint32_t)(ks * 16 + krl);
            #pragma unroll
            for (int j = 0; j < 4; j++) {
                uint32_t so = krow * 256 + (((cbas + j) ^ krl) * 16);
                ldsm2t(fb[j], base + 2 * TILEB_ + so);
            }
            // product-major: hi product then lo product
            #pragma unroll
            for (int i = 0; i < 4; i++)
                #pragma unroll
                for (int j = 0; j < 4; j++)
                    mma16816(acc[i][j], fa_h[i], fb[j]);
            #pragma unroll
            for (int i = 0; i < 4; i++)
                #pragma unroll
                for (int j = 0; j < 4; j++)
                    mma16816(acc[i][j], fa_l[i], fb[j]);
        }
        __syncthreads();
    }

    // ---- epilogue ----
    const int g  = lane >> 2, tg = lane & 3;
    const size_t row0 = ar0 + wm, col0 = bc0 + wn;
    #pragma unroll
    for (int i = 0; i < 4; i++) {
        #pragma unroll
        for (int j = 0; j < 4; j++) {
            size_t col = col0 + j * 8 + tg * 2;
            float bx = 0.0f, by = 0.0f;
            if (BIAS) { bx = bias[col]; by = bias[col + 1]; }
            #pragma unroll
            for (int half = 0; half < 2; half++) {
                size_t row = row0 + i * 16 + g + half * 8;
                float vx = acc[i][j][2 * half + 0] + bx;
                float vy = acc[i][j][2 * half + 1] + by;
                size_t gi = row * (size_t)N + col;
                if (RES) { vx += res[gi]; vy += res[gi + 1]; }
                if (RELU) { vx = fmaxf(vx, 0.0f); vy = fmaxf(vy, 0.0f); }
                if (OSPLIT) {
                    __half hx = __float2half_rn(vx);
                    __half hy = __float2half_rn(vy);
                    Oh[gi >> 1] = __halves2half2(hx, hy);
                    Ol[gi >> 1] = __halves2half2(
                        __float2half_rn(vx - __half2float(hx)),
                        __float2half_rn(vy - __half2float(hy)));
                } else {
                    float2 o; o.x = vx; o.y = vy;
                    *(float2*)(C + gi) = o;
                }
            }
        }
    }
}

// ------------------------- query-tiled causal attention (QT=16) -------------
#define QT_   16
#define SPAD_ 1032
#define ATT_SMEM_ ((QT_ * SPAD_ + QT_) * 4)
__global__ __launch_bounds__(256) void attention2_k(
    const float* __restrict__ q, const float* __restrict__ k,
    const float* __restrict__ v,
    __half* __restrict__ oh, __half* __restrict__ ol)
{
    extern __shared__ float S[];          // [QT_][SPAD_] + Rinv[QT_]
    float* Rinv = S + QT_ * SPAD_;

    int qt = blockIdx.x, h = blockIdx.y, b = blockIdx.z;
    int q0 = qt * QT_;
    int nmax = q0 + QT_;
    int tid = threadIdx.x;

    // ---- phase 1: scores.  qi = tid&15, jg = tid>>4 (16 slots) ----
    {
        int qi = tid & 15;
        int jg = tid >> 4;
        const float* qp = q + (((size_t)b * S_ + q0 + qi) * H_ + h) * HS_;
        float4 qr[16];
        #pragma unroll
        for (int d = 0; d < 16; d++) qr[d] = *(const float4*)(qp + 4 * d);
        int nq = q0 + qi + 1;
        for (int j = jg; j < nq; j += 16) {
            const float* kp = k + (((size_t)b * S_ + j) * H_ + h) * HS_;
            float dot = 0.0f;
            #pragma unroll
            for (int d = 0; d < 16; d++) {
                float4 kk = *(const float4*)(kp + 4 * d);
                dot += kk.x * qr[d].x + kk.y * qr[d].y + kk.z * qr[d].z + kk.w * qr[d].w;
            }
            S[qi * SPAD_ + j] = dot * SCALE_;
        }
    }
    __syncthreads();

    // ---- phase 2: softmax.  warp w handles queries 2w, 2w+1 ----
    {
        int w = tid >> 5, l = tid & 31;
        #pragma unroll
        for (int qq = 0; qq < 2; qq++) {
            int qi = 2 * w + qq;
            int nq = q0 + qi + 1;
            float m = -1e30f;
            for (int j = l; j < nq; j += 32) m = fmaxf(m, S[qi * SPAD_ + j]);
            #pragma unroll
            for (int st = 16; st > 0; st >>= 1)
                m = fmaxf(m, __shfl_xor_sync(0xffffffff, m, st));
            float sum = 0.0f;
            for (int j = l; j < nq; j += 32) {
                float e = __expf(S[qi * SPAD_ + j] - m);
                S[qi * SPAD_ + j] = e;
                sum += e;
            }
            #pragma unroll
            for (int st = 16; st > 0; st >>= 1)
                sum += __shfl_xor_sync(0xffffffff, sum, st);
            for (int j = nq + l; j < nmax; j += 32) S[qi * SPAD_ + j] = 0.0f;
            if (l == 0) Rinv[qi] = 1.0f / sum;
        }
    }
    __syncthreads();

    // ---- phase 3: O = P @ V.  d4 = tid&15, jg = tid>>4 ----
    float acc[QT_][4];
    {
        int d4 = tid & 15;
        int jg = tid >> 4;
        #pragma unroll
        for (int qi = 0; qi < QT_; qi++)
            #pragma unroll
            for (int cc = 0; cc < 4; cc++) acc[qi][cc] = 0.0f;
        for (int j = jg; j < nmax; j += 16) {
            float4 vv = *(const float4*)(v + (((size_t)b * S_ + j) * H_ + h) * HS_ + d4 * 4);
            #pragma unroll
            for (int qi = 0; qi < QT_; qi++) {
                float p = S[qi * SPAD_ + j];
                acc[qi][0] += p * vv.x; acc[qi][1] += p * vv.y;
                acc[qi][2] += p * vv.z; acc[qi][3] += p * vv.w;
            }
        }
    }
    __syncthreads();
    // scatter partials (reuse S) then reduce 16 jg groups
    {
        int d4 = tid & 15;
        int jg = tid >> 4;
        #pragma unroll
        for (int qi = 0; qi < QT_; qi++)
            #pragma unroll
            for (int cc = 0; cc < 4; cc++)
                S[jg * 1024 + qi * 64 + d4 * 4 + cc] = acc[qi][cc];
    }
    __syncthreads();
    {
        #pragma unroll
        for (int e = tid; e < 1024; e += 256) {
            int qi = e >> 6, d = e & 63;
            float sum = 0.0f;
            #pragma unroll
            for (int jg = 0; jg < 16; jg++) sum += S[jg * 1024 + e];
            float val = sum * Rinv[qi];
            size_t gi = (((size_t)b * S_ + q0 + qi) * H_ + h) * HS_ + d;
            __half hv = __float2half_rn(val);
            oh[gi] = hv;
            ol[gi] = __float2half_rn(val - __half2float(hv));
        }
    }
}

// ------------------------- driver -------------------------------------------
extern "C" void kernel_launch(void* const* d_in, const int* in_sizes, int n_in,
                              void* d_out, int out_size)
{
    const int*   idx   = (const int*)  d_in[0];
    const float* tok   = (const float*)d_in[1];
    const float* pos   = (const float*)d_in[2];
    const float* ln1g  = (const float*)d_in[3];
    const float* ln1b  = (const float*)d_in[4];
    const float* ln2g  = (const float*)d_in[5];
    const float* ln2b  = (const float*)d_in[6];
    const float* wq    = (const float*)d_in[7];
    const float* wk    = (const float*)d_in[8];
    const float* wv    = (const float*)d_in[9];
    const float* wo    = (const float*)d_in[10];
    const float* bo    = (const float*)d_in[11];
    const float* w1    = (const float*)d_in[12];
    const float* b1    = (const float*)d_in[13];
    const float* w2    = (const float*)d_in[14];
    const float* b2    = (const float*)d_in[15];
    const float* lnfg  = (const float*)d_in[16];
    const float* lnfb  = (const float*)d_in[17];
    const float* whead = (const float*)d_in[18];
    const float* bhead = (const float*)d_in[19];
    float* out = (float*)d_out;

    float *x, *xn, *qkv;
    __half *ah, *al, *hh, *hl, *wh;
    cudaGetSymbolAddress((void**)&x,   g_x);
    cudaGetSymbolAddress((void**)&xn,  g_xn);
    cudaGetSymbolAddress((void**)&qkv, g_qkv);
    cudaGetSymbolAddress((void**)&ah,  g_ah);
    cudaGetSymbolAddress((void**)&al,  g_al);
    cudaGetSymbolAddress((void**)&hh,  g_hh);
    cudaGetSymbolAddress((void**)&hl,  g_hl);
    cudaGetSymbolAddress((void**)&wh,  g_wh);

    cudaFuncSetAttribute(mma_gemm_k<false,false,false,false>, cudaFuncAttributeMaxDynamicSharedMemorySize, SMTOT_);
    cudaFuncSetAttribute(mma_gemm_k<true,true,false,false>,   cudaFuncAttributeMaxDynamicSharedMemorySize, SMTOT_);
    cudaFuncSetAttribute(mma_gemm_k<true,false,true,true>,    cudaFuncAttributeMaxDynamicSharedMemorySize, SMTOT_);
    cudaFuncSetAttribute(mma_gemm_k<true,false,false,false>,  cudaFuncAttributeMaxDynamicSharedMemorySize, SMTOT_);
    cudaFuncSetAttribute(attention2_k, cudaFuncAttributeMaxDynamicSharedMemorySize, ATT_SMEM_);

    dim3 blk(256);

    // ---- weight fp16 conversion (layout-preserving, fully coalesced) ----
    {
        int nQ = (int)(4 * DD_ / 4);
        int nF = (int)(16 * DD_ / 4);
        int nH = (int)((size_t)D_ * V_ / 4);
        wsplit_k<<<(nQ + 255)/256, blk>>>((const float4*)wq, (__half2*)(wh + WQ_OFF_), nQ);
        wsplit_k<<<(nQ + 255)/256, blk>>>((const float4*)wk, (__half2*)(wh + WK_OFF_), nQ);
        wsplit_k<<<(nQ + 255)/256, blk>>>((const float4*)wv, (__half2*)(wh + WV_OFF_), nQ);
        wsplit_k<<<(nQ + 255)/256, blk>>>((const float4*)wo, (__half2*)(wh + WO_OFF_), nQ);
        wsplit_k<<<(nF + 255)/256, blk>>>((const float4*)w1, (__half2*)(wh + W1_OFF_), nF);
        wsplit_k<<<(nF + 255)/256, blk>>>((const float4*)w2, (__half2*)(wh + W2_OFF_), nF);
        wsplit_k<<<(nH + 255)/256, blk>>>((const float4*)whead, (__half2*)(wh + WH_OFF_), nH);
    }

    embed_k<<<M_, blk>>>(idx, (const float4*)tok, (const float4*)pos, (float4*)x);

    for (int l = 0; l < L_; l++) {
        size_t oq = WQ_OFF_ + (size_t)l * DD_;
        size_t oo = WO_OFF_ + (size_t)l * DD_;
        size_t o1 = W1_OFF_ + (size_t)l * 4 * DD_;
        size_t o2 = W2_OFF_ + (size_t)l * 4 * DD_;

        layernorm_k<<<M_, blk>>>((const float4*)x, (const float4*)(ln1g + l * D_),
                                 (const float4*)(ln1b + l * D_), (float4*)xn,
                                 (__half2*)ah, (__half2*)al);

        // fused QKV
        mma_gemm_k<false,false,false,false><<<dim3(M_/128, D_/128, 3), blk, SMTOT_>>>(
            M_, D_, D_, ah, al, wh + oq, nullptr, nullptr, qkv,
            nullptr, nullptr, 4 * DD_, MD_);

        attention2_k<<<dim3(S_ / QT_, H_, B_), 256, ATT_SMEM_>>>(
            qkv, qkv + MD_, qkv + 2 * MD_, ah, al);

        // x = xn + att @ wo + bo
        mma_gemm_k<true,true,false,false><<<dim3(M_/128, D_/128), blk, SMTOT_>>>(
            M_, D_, D_, ah, al, wh + oo, bo + l * D_, xn, x,
            nullptr, nullptr, 0, 0);

        layernorm_k<<<M_, blk>>>((const float4*)x, (const float4*)(ln2g + l * D_),
                                 (const float4*)(ln2b + l * D_), (float4*)xn,
                                 (__half2*)ah, (__half2*)al);

        // h = relu(xn @ w1 + b1)  -> fp16 hi/lo directly
        mma_gemm_k<true,false,true,true><<<dim3(M_/128, DFF_/128), blk, SMTOT_>>>(
            M_, DFF_, D_, ah, al, wh + o1,
            b1 + (size_t)l * DFF_, nullptr, nullptr,
            (__half2*)hh, (__half2*)hl, 0, 0);

        // x = xn + h @ w2 + b2
        mma_gemm_k<true,true,false,false><<<dim3(M_/128, D_/128), blk, SMTOT_>>>(
            M_, D_, DFF_, hh, hl, wh + o2,
            b2 + l * D_, xn, x, nullptr, nullptr, 0, 0);
    }

    layernorm_k<<<M_, blk>>>((const float4*)x, (const float4*)lnfg,
                             (const float4*)lnfb, (float4*)xn,
                             (__half2*)ah, (__half2*)al);

    // logits = xn @ w_head + b_head
    mma_gemm_k<true,false,false,false><<<dim3(M_/128, V_/128), blk, SMTOT_>>>(
        M_, V_, D_, ah, al, wh + WH_OFF_,
        bhead, nullptr, out, nullptr, nullptr, 0, 0);
}